// round 1
// baseline (speedup 1.0000x reference)
#include <cuda_runtime.h>
#include <math.h>

#define NB 512
#define NH 1024
#define NS 64
#define NM 10
#define CAT_LD 1040   // padded row stride for concat buffer (K=1034 actual)

// ---------------- scratch (device globals; no allocations allowed) ----------
__device__ float g_u[NB * NH];          // h_last @ attn_W
__device__ float g_cat[NB * CAT_LD];    // [motion(10) | context(1024)] padded
__device__ float g_x0[NB * NH];         // pre_linear output (GRU0 input)
__device__ float g_gi[NB * 3 * NH];     // input gates scratch (reused per layer)
__device__ float g_gh[NB * 3 * NH];     // hidden gates scratch (reused per layer)
__device__ float g_h0[NB * NH];
__device__ float g_h1[NB * NH];

__device__ __forceinline__ float warp_sum(float v) {
#pragma unroll
    for (int o = 16; o; o >>= 1) v += __shfl_xor_sync(0xffffffffu, v, o);
    return v;
}

// ---------------- SGEMM: C[M,N] = A[M,K] * op(B) + bias --------------------
// TB=true : B stored [N,K] row-major (dot along contiguous rows, "x @ W^T")
// TB=false: B stored [K,N] row-major
// Tile 128x64x16, 256 threads, 8x4 accum per thread.
template <bool TB>
__global__ __launch_bounds__(256) void gemm128x64(
    const float* __restrict__ A, const float* __restrict__ B,
    const float* __restrict__ bias, float* __restrict__ C,
    int M, int N, int K, int lda, int ldb, int ldc, int alignedB)
{
    __shared__ float As[16][132];  // [k][m], padded
    __shared__ float Bs[16][68];   // [k][n], padded

    const int tid = threadIdx.x;
    const int m0 = blockIdx.y * 128;
    const int n0 = blockIdx.x * 64;

    float acc[8][4];
#pragma unroll
    for (int i = 0; i < 8; i++)
#pragma unroll
        for (int j = 0; j < 4; j++) acc[i][j] = 0.f;

    const int tm = (tid >> 4) * 8;   // 0..120
    const int tn = (tid & 15) * 4;   // 0..60

    for (int k0 = 0; k0 < K; k0 += 16) {
        // ---- load A tile (transpose into As[k][m]) ----
        {
            const int lm = tid >> 1;
            const int kb = (tid & 1) * 8;
            const float* ap = A + (size_t)(m0 + lm) * lda + k0 + kb;
            if (k0 + 16 <= K) {
                float4 v0 = *(const float4*)ap;
                float4 v1 = *(const float4*)(ap + 4);
                As[kb + 0][lm] = v0.x; As[kb + 1][lm] = v0.y;
                As[kb + 2][lm] = v0.z; As[kb + 3][lm] = v0.w;
                As[kb + 4][lm] = v1.x; As[kb + 5][lm] = v1.y;
                As[kb + 6][lm] = v1.z; As[kb + 7][lm] = v1.w;
            } else {
#pragma unroll
                for (int i = 0; i < 8; i++) {
                    int kk = k0 + kb + i;
                    As[kb + i][lm] = (kk < K) ? ap[i] : 0.f;
                }
            }
        }
        // ---- load B tile into Bs[k][n] ----
        if (TB) {
            const int ln = tid >> 2;
            const int kb = (tid & 3) * 4;
            const float* bp = B + (size_t)(n0 + ln) * ldb + k0 + kb;
            if (alignedB && (k0 + 16 <= K)) {
                float4 v = *(const float4*)bp;
                Bs[kb + 0][ln] = v.x; Bs[kb + 1][ln] = v.y;
                Bs[kb + 2][ln] = v.z; Bs[kb + 3][ln] = v.w;
            } else {
#pragma unroll
                for (int i = 0; i < 4; i++) {
                    int kk = k0 + kb + i;
                    Bs[kb + i][ln] = (kk < K) ? bp[i] : 0.f;
                }
            }
        } else {
            const int ln = (tid & 15) * 4;
            const int lk = tid >> 4;
            const int kk = k0 + lk;
            float4 v = make_float4(0.f, 0.f, 0.f, 0.f);
            if (kk < K) v = *(const float4*)(B + (size_t)kk * ldb + n0 + ln);
            *(float4*)&Bs[lk][ln] = v;
        }
        __syncthreads();

#pragma unroll
        for (int k = 0; k < 16; k++) {
            float4 a0 = *(const float4*)&As[k][tm];
            float4 a1 = *(const float4*)&As[k][tm + 4];
            float4 bv = *(const float4*)&Bs[k][tn];
            float a[8] = {a0.x, a0.y, a0.z, a0.w, a1.x, a1.y, a1.z, a1.w};
            float bb[4] = {bv.x, bv.y, bv.z, bv.w};
#pragma unroll
            for (int i = 0; i < 8; i++)
#pragma unroll
                for (int j = 0; j < 4; j++)
                    acc[i][j] = fmaf(a[i], bb[j], acc[i][j]);
        }
        __syncthreads();
    }

    float4 b4 = make_float4(0.f, 0.f, 0.f, 0.f);
    if (bias) b4 = *(const float4*)&bias[n0 + tn];
#pragma unroll
    for (int i = 0; i < 8; i++) {
        float4 v = make_float4(acc[i][0] + b4.x, acc[i][1] + b4.y,
                               acc[i][2] + b4.z, acc[i][3] + b4.w);
        *(float4*)&C[(size_t)(m0 + tm + i) * ldc + n0 + tn] = v;
    }
}

// ---------------- attention: energies + softmax + context + concat ----------
// 1 block per batch row b. energies[b,s] = u[b,:] . enc[s,b,:]  (attn_b term
// is a per-b constant -> softmax invariant -> dropped)
__global__ __launch_bounds__(256) void attn_kernel(
    const float* __restrict__ enc, const float* __restrict__ u,
    const float* __restrict__ motion, float* __restrict__ attn_out,
    float* __restrict__ cat)
{
    const int b = blockIdx.x;
    const int tid = threadIdx.x;
    const int lane = tid & 31, warp = tid >> 5;
    __shared__ float e[NS];

    float ureg[32];
    const float* ub = u + (size_t)b * NH;
#pragma unroll
    for (int i = 0; i < 32; i++) ureg[i] = ub[i * 32 + lane];

    for (int s = warp; s < NS; s += 8) {
        const float* ep = enc + ((size_t)s * NB + b) * NH;
        float acc = 0.f;
#pragma unroll
        for (int i = 0; i < 32; i++) acc = fmaf(ep[i * 32 + lane], ureg[i], acc);
        acc = warp_sum(acc);
        if (lane == 0) e[s] = acc;
    }
    __syncthreads();

    if (tid < 32) {
        float v0 = e[tid], v1 = e[tid + 32];
        float m = fmaxf(v0, v1);
#pragma unroll
        for (int o = 16; o; o >>= 1) m = fmaxf(m, __shfl_xor_sync(0xffffffffu, m, o));
        float e0 = expf(v0 - m), e1 = expf(v1 - m);
        float s = warp_sum(e0 + e1);
        float inv = 1.f / s;
        e[tid] = e0 * inv;
        e[tid + 32] = e1 * inv;
    }
    __syncthreads();

    if (tid < NS) attn_out[(size_t)b * NS + tid] = e[tid];
    if (tid < NM) cat[(size_t)b * CAT_LD + tid] = motion[(size_t)b * NM + tid];

#pragma unroll
    for (int j = 0; j < 4; j++) {
        const int h = tid + j * 256;
        float acc = 0.f;
#pragma unroll 8
        for (int s = 0; s < NS; s++)
            acc = fmaf(e[s], enc[((size_t)s * NB + b) * NH + h], acc);
        cat[(size_t)b * CAT_LD + NM + h] = acc;
    }
}

// ---------------- GRU gate pointwise ----------------------------------------
__global__ __launch_bounds__(256) void gate_kernel(
    const float* __restrict__ gi, const float* __restrict__ gh,
    const float* __restrict__ hprev, float* __restrict__ hnew,
    float* __restrict__ out_h)
{
    const int idx = blockIdx.x * blockDim.x + threadIdx.x;  // < NB*NH
    const int b = idx >> 10, n = idx & (NH - 1);
    const float* gib = gi + (size_t)b * 3 * NH;
    const float* ghb = gh + (size_t)b * 3 * NH;
    float ir = gib[n], iz = gib[NH + n], inn = gib[2 * NH + n];
    float hr = ghb[n], hz = ghb[NH + n], hn = ghb[2 * NH + n];
    float r = 1.f / (1.f + expf(-(ir + hr)));
    float z = 1.f / (1.f + expf(-(iz + hz)));
    float nn = tanhf(inn + r * hn);
    float h = (1.f - z) * nn + z * hprev[idx];
    hnew[idx] = h;
    out_h[idx] = h;
}

// ---------------- post linear: [B,1024] -> [B,10] ---------------------------
__global__ __launch_bounds__(128) void post_kernel(
    const float* __restrict__ h1, const float* __restrict__ W,
    const float* __restrict__ bias, float* __restrict__ out)
{
    const int b = blockIdx.x;
    const int tid = threadIdx.x;
    float acc[10];
#pragma unroll
    for (int o = 0; o < 10; o++) acc[o] = 0.f;
    for (int h = tid; h < NH; h += 128) {
        float x = h1[(size_t)b * NH + h];
#pragma unroll
        for (int o = 0; o < 10; o++) acc[o] = fmaf(x, W[(size_t)o * NH + h], acc[o]);
    }
    __shared__ float red[128];
#pragma unroll
    for (int o = 0; o < 10; o++) {
        red[tid] = acc[o];
        __syncthreads();
        for (int st = 64; st; st >>= 1) {
            if (tid < st) red[tid] += red[tid + st];
            __syncthreads();
        }
        if (tid == 0) out[(size_t)b * 10 + o] = red[0] + bias[o];
        __syncthreads();
    }
}

// ---------------- host launch ------------------------------------------------
extern "C" void kernel_launch(void* const* d_in, const int* in_sizes, int n_in,
                              void* d_out, int out_size)
{
    const float* motion      = (const float*)d_in[0];
    const float* last_hidden = (const float*)d_in[1];
    const float* enc         = (const float*)d_in[2];
    const float* attn_W      = (const float*)d_in[3];
    /* d_in[4] = attn_b: unused (softmax shift-invariant) */
    const float* pre_W  = (const float*)d_in[5];
    const float* pre_b  = (const float*)d_in[6];
    const float* Wih0   = (const float*)d_in[7];
    const float* Whh0   = (const float*)d_in[8];
    const float* bih0   = (const float*)d_in[9];
    const float* bhh0   = (const float*)d_in[10];
    const float* Wih1   = (const float*)d_in[11];
    const float* Whh1   = (const float*)d_in[12];
    const float* bih1   = (const float*)d_in[13];
    const float* bhh1   = (const float*)d_in[14];
    const float* post_W = (const float*)d_in[15];
    const float* post_b = (const float*)d_in[16];

    float* out        = (float*)d_out;
    float* out_output = out;                               // [512,10]
    float* out_h0     = out + NB * 10;                     // hidden[0]
    float* out_h1     = out + NB * 10 + NB * NH;           // hidden[1]
    float* out_attn   = out + NB * 10 + 2 * NB * NH;       // [512,1,64]

    float *u, *cat, *x0, *gi, *gh, *h0, *h1;
    cudaGetSymbolAddress((void**)&u,   g_u);
    cudaGetSymbolAddress((void**)&cat, g_cat);
    cudaGetSymbolAddress((void**)&x0,  g_x0);
    cudaGetSymbolAddress((void**)&gi,  g_gi);
    cudaGetSymbolAddress((void**)&gh,  g_gh);
    cudaGetSymbolAddress((void**)&h0,  g_h0);
    cudaGetSymbolAddress((void**)&h1,  g_h1);

    const float* hL0 = last_hidden;                 // last_hidden[0]
    const float* hL1 = last_hidden + NB * NH;       // last_hidden[1] (= [-1])

    // 1) u = h_last @ attn_W   (NN: attn_W is [K=H, N=H] row-major here)
    gemm128x64<false><<<dim3(NH / 64, NB / 128), 256>>>(
        hL1, attn_W, nullptr, u, NB, NH, NH, NH, NH, NH, 1);

    // 2) energies -> softmax -> attn_weights out + context into concat buffer
    attn_kernel<<<NB, 256>>>(enc, u, motion, out_attn, cat);

    // 3) rnn_input = cat @ pre_W^T + pre_b   (K = 1034, pre_W rows not 16B aligned)
    gemm128x64<true><<<dim3(NH / 64, NB / 128), 256>>>(
        cat, pre_W, pre_b, x0, NB, NH, NH + NM, CAT_LD, NH + NM, NH, 0);

    // 4) GRU layer 0
    gemm128x64<true><<<dim3(3 * NH / 64, NB / 128), 256>>>(
        x0, Wih0, bih0, gi, NB, 3 * NH, NH, NH, NH, 3 * NH, 1);
    gemm128x64<true><<<dim3(3 * NH / 64, NB / 128), 256>>>(
        hL0, Whh0, bhh0, gh, NB, 3 * NH, NH, NH, NH, 3 * NH, 1);
    gate_kernel<<<NB * NH / 256, 256>>>(gi, gh, hL0, h0, out_h0);

    // 5) GRU layer 1
    gemm128x64<true><<<dim3(3 * NH / 64, NB / 128), 256>>>(
        h0, Wih1, bih1, gi, NB, 3 * NH, NH, NH, NH, 3 * NH, 1);
    gemm128x64<true><<<dim3(3 * NH / 64, NB / 128), 256>>>(
        hL1, Whh1, bhh1, gh, NB, 3 * NH, NH, NH, NH, 3 * NH, 1);
    gate_kernel<<<NB * NH / 256, 256>>>(gi, gh, hL1, h1, out_h1);

    // 6) output = h1 @ post_W^T + post_b
    post_kernel<<<NB, 128>>>(h1, post_W, post_b, out_output);
}

// round 2
// speedup vs baseline: 1.3814x; 1.3814x over previous
#include <cuda_runtime.h>
#include <math.h>

#define NB 512
#define NH 1024
#define NS 64
#define NM 10
#define CAT_LD 1040   // padded row stride for concat buffer (K=1034 actual -> 1040)

// ---------------- scratch (device globals; no allocations allowed) ----------
__device__ float g_u[NB * NH];            // h_last @ attn_W
__device__ float g_cat[NB * CAT_LD];      // [motion(10) | context(1024) | 0-pad]
__device__ float g_x0[NB * NH];           // pre_linear output (GRU0 input)
__device__ float g_gi[NB * 3 * NH];
__device__ float g_gh[NB * 3 * NH];
__device__ float g_preW[NH * CAT_LD];     // pre_W repacked to padded stride

__device__ __forceinline__ float warp_sum(float v) {
#pragma unroll
    for (int o = 16; o; o >>= 1) v += __shfl_xor_sync(0xffffffffu, v, o);
    return v;
}

// ---------------- repack pre_W [1024,1034] -> [1024,1040] zero-padded -------
__global__ __launch_bounds__(256) void repack_preW(const float* __restrict__ W,
                                                   float* __restrict__ out)
{
    const int n = blockIdx.x;
    for (int k = threadIdx.x; k < CAT_LD; k += 256)
        out[(size_t)n * CAT_LD + k] = (k < NH + NM) ? W[(size_t)n * (NH + NM) + k] : 0.f;
}

// ---------------- pipelined SGEMM: C = A * op(B) + bias ---------------------
// TB=true : B stored [N,K] row-major ("x @ W^T"),  TB=false: B stored [K,N].
// Tile 128x64x16, 256 threads, 8x4 per thread, double-buffered smem with
// register-staged global prefetch. blockIdx.z selects an independent
// (A,B,bias,C) problem -> batches the two GRU gate GEMMs into one launch.
// Requires: M%128==0, N%64==0, K%16==0, all pointers/strides float4-aligned.
template <bool TB>
__global__ __launch_bounds__(256) void gemm_pipe(
    const float* __restrict__ A0, const float* __restrict__ A1v,
    const float* __restrict__ B0, const float* __restrict__ B1v,
    const float* __restrict__ bias0, const float* __restrict__ bias1v,
    float* __restrict__ C0, float* __restrict__ C1v,
    int M, int N, int K, int lda, int ldb, int ldc)
{
    __shared__ float As[2][16][132];
    __shared__ float Bs[2][16][68];

    const int z = blockIdx.z;
    const float* A = z ? A1v : A0;
    const float* B = z ? B1v : B0;
    const float* bias = z ? bias1v : bias0;
    float* C = z ? C1v : C0;

    const int tid = threadIdx.x;
    const int m0 = blockIdx.y * 128;
    const int n0 = blockIdx.x * 64;

    float acc[8][4];
#pragma unroll
    for (int i = 0; i < 8; i++)
#pragma unroll
        for (int j = 0; j < 4; j++) acc[i][j] = 0.f;

    const int tm = (tid >> 4) * 8;
    const int tn = (tid & 15) * 4;

    // global load assignments
    const int a_lm = tid >> 1;               // 0..127
    const int a_kb = (tid & 1) * 8;          // 0 or 8
    const float* Ap = A + (size_t)(m0 + a_lm) * lda + a_kb;

    const int b_ln_t = tid >> 2;             // TB: 0..63
    const int b_kb_t = (tid & 3) * 4;        // TB: 0,4,8,12
    const int b_lk_n = tid >> 4;             // NN: 0..15
    const int b_ln_n = (tid & 15) * 4;       // NN: 0..60
    const float* Bp = TB ? (B + (size_t)(n0 + b_ln_t) * ldb + b_kb_t)
                         : (B + (size_t)b_lk_n * ldb + n0 + b_ln_n);

    float ar[8];
    float br[4];

    auto g_load = [&]() {
        float4 v0 = *(const float4*)Ap;
        float4 v1 = *(const float4*)(Ap + 4);
        ar[0] = v0.x; ar[1] = v0.y; ar[2] = v0.z; ar[3] = v0.w;
        ar[4] = v1.x; ar[5] = v1.y; ar[6] = v1.z; ar[7] = v1.w;
        float4 bv = *(const float4*)Bp;
        br[0] = bv.x; br[1] = bv.y; br[2] = bv.z; br[3] = bv.w;
        Ap += 16;
        Bp += TB ? 16 : (size_t)16 * ldb;
    };
    auto s_store = [&](int buf) {
#pragma unroll
        for (int i = 0; i < 8; i++) As[buf][a_kb + i][a_lm] = ar[i];
        if (TB) {
#pragma unroll
            for (int i = 0; i < 4; i++) Bs[buf][b_kb_t + i][b_ln_t] = br[i];
        } else {
            *(float4*)&Bs[buf][b_lk_n][b_ln_n] = make_float4(br[0], br[1], br[2], br[3]);
        }
    };

    const int nk = K >> 4;
    g_load();
    s_store(0);
    __syncthreads();

    for (int t = 0; t < nk; t++) {
        const bool more = (t + 1 < nk);
        if (more) g_load();
        const int buf = t & 1;
#pragma unroll
        for (int k = 0; k < 16; k++) {
            float4 a0 = *(const float4*)&As[buf][k][tm];
            float4 a1 = *(const float4*)&As[buf][k][tm + 4];
            float4 bv = *(const float4*)&Bs[buf][k][tn];
            float a[8] = {a0.x, a0.y, a0.z, a0.w, a1.x, a1.y, a1.z, a1.w};
            float bb[4] = {bv.x, bv.y, bv.z, bv.w};
#pragma unroll
            for (int i = 0; i < 8; i++)
#pragma unroll
                for (int j = 0; j < 4; j++)
                    acc[i][j] = fmaf(a[i], bb[j], acc[i][j]);
        }
        if (more) {
            s_store(buf ^ 1);
            __syncthreads();
        }
    }

    float4 b4 = make_float4(0.f, 0.f, 0.f, 0.f);
    if (bias) b4 = *(const float4*)&bias[n0 + tn];
#pragma unroll
    for (int i = 0; i < 8; i++) {
        float4 v = make_float4(acc[i][0] + b4.x, acc[i][1] + b4.y,
                               acc[i][2] + b4.z, acc[i][3] + b4.w);
        *(float4*)&C[(size_t)(m0 + tm + i) * ldc + n0 + tn] = v;
    }
}

// ---------------- attention: energies + softmax + context + concat ----------
__global__ __launch_bounds__(256) void attn_kernel(
    const float* __restrict__ enc, const float* __restrict__ u,
    const float* __restrict__ motion, float* __restrict__ attn_out,
    float* __restrict__ cat)
{
    const int b = blockIdx.x;
    const int tid = threadIdx.x;
    const int lane = tid & 31, warp = tid >> 5;
    __shared__ float e[NS];

    float ureg[32];
    const float* ub = u + (size_t)b * NH;
#pragma unroll
    for (int i = 0; i < 32; i++) ureg[i] = ub[i * 32 + lane];

    for (int s = warp; s < NS; s += 8) {
        const float* ep = enc + ((size_t)s * NB + b) * NH;
        float acc = 0.f;
#pragma unroll
        for (int i = 0; i < 32; i++) acc = fmaf(ep[i * 32 + lane], ureg[i], acc);
        acc = warp_sum(acc);
        if (lane == 0) e[s] = acc;
    }
    __syncthreads();

    if (tid < 32) {
        float v0 = e[tid], v1 = e[tid + 32];
        float m = fmaxf(v0, v1);
#pragma unroll
        for (int o = 16; o; o >>= 1) m = fmaxf(m, __shfl_xor_sync(0xffffffffu, m, o));
        float e0 = expf(v0 - m), e1 = expf(v1 - m);
        float s = warp_sum(e0 + e1);
        float inv = 1.f / s;
        e[tid] = e0 * inv;
        e[tid + 32] = e1 * inv;
    }
    __syncthreads();

    if (tid < NS) attn_out[(size_t)b * NS + tid] = e[tid];
    if (tid < NM) cat[(size_t)b * CAT_LD + tid] = motion[(size_t)b * NM + tid];
    if (tid >= NM && tid < NM + (CAT_LD - NH - NM))
        cat[(size_t)b * CAT_LD + NH + tid] = 0.f;   // zero pad cols 1034..1039

#pragma unroll
    for (int j = 0; j < 4; j++) {
        const int h = tid + j * 256;
        float acc = 0.f;
#pragma unroll 8
        for (int s = 0; s < NS; s++)
            acc = fmaf(e[s], enc[((size_t)s * NB + b) * NH + h], acc);
        cat[(size_t)b * CAT_LD + NM + h] = acc;
    }
}

// ---------------- GRU gate pointwise ----------------------------------------
__global__ __launch_bounds__(256) void gate_kernel(
    const float* __restrict__ gi, const float* __restrict__ gh,
    const float* __restrict__ hprev, float* __restrict__ out_h)
{
    const int idx = blockIdx.x * blockDim.x + threadIdx.x;
    const int b = idx >> 10, n = idx & (NH - 1);
    const float* gib = gi + (size_t)b * 3 * NH;
    const float* ghb = gh + (size_t)b * 3 * NH;
    float ir = gib[n], iz = gib[NH + n], inn = gib[2 * NH + n];
    float hr = ghb[n], hz = ghb[NH + n], hn = ghb[2 * NH + n];
    float r = 1.f / (1.f + expf(-(ir + hr)));
    float z = 1.f / (1.f + expf(-(iz + hz)));
    float nn = tanhf(inn + r * hn);
    out_h[idx] = (1.f - z) * nn + z * hprev[idx];
}

// ---------------- post linear: [B,1024] -> [B,10] ---------------------------
__global__ __launch_bounds__(128) void post_kernel(
    const float* __restrict__ h1, const float* __restrict__ W,
    const float* __restrict__ bias, float* __restrict__ out)
{
    const int b = blockIdx.x;
    const int tid = threadIdx.x;
    float acc[10];
#pragma unroll
    for (int o = 0; o < 10; o++) acc[o] = 0.f;
    for (int h = tid; h < NH; h += 128) {
        float x = h1[(size_t)b * NH + h];
#pragma unroll
        for (int o = 0; o < 10; o++) acc[o] = fmaf(x, W[(size_t)o * NH + h], acc[o]);
    }
    __shared__ float red[128];
#pragma unroll
    for (int o = 0; o < 10; o++) {
        red[tid] = acc[o];
        __syncthreads();
        for (int st = 64; st; st >>= 1) {
            if (tid < st) red[tid] += red[tid + st];
            __syncthreads();
        }
        if (tid == 0) out[(size_t)b * 10 + o] = red[0] + bias[o];
        __syncthreads();
    }
}

// ---------------- host launch ------------------------------------------------
extern "C" void kernel_launch(void* const* d_in, const int* in_sizes, int n_in,
                              void* d_out, int out_size)
{
    const float* motion      = (const float*)d_in[0];
    const float* last_hidden = (const float*)d_in[1];
    const float* enc         = (const float*)d_in[2];
    const float* attn_W      = (const float*)d_in[3];
    /* d_in[4] = attn_b: unused (softmax shift-invariant) */
    const float* pre_W  = (const float*)d_in[5];
    const float* pre_b  = (const float*)d_in[6];
    const float* Wih0   = (const float*)d_in[7];
    const float* Whh0   = (const float*)d_in[8];
    const float* bih0   = (const float*)d_in[9];
    const float* bhh0   = (const float*)d_in[10];
    const float* Wih1   = (const float*)d_in[11];
    const float* Whh1   = (const float*)d_in[12];
    const float* bih1   = (const float*)d_in[13];
    const float* bhh1   = (const float*)d_in[14];
    const float* post_W = (const float*)d_in[15];
    const float* post_b = (const float*)d_in[16];

    float* out        = (float*)d_out;
    float* out_output = out;                               // [512,10]
    float* out_h0     = out + NB * 10;                     // hidden[0]
    float* out_h1     = out + NB * 10 + NB * NH;           // hidden[1]
    float* out_attn   = out + NB * 10 + 2 * NB * NH;       // [512,1,64]

    float *u, *cat, *x0, *gi, *gh, *preW;
    cudaGetSymbolAddress((void**)&u,    g_u);
    cudaGetSymbolAddress((void**)&cat,  g_cat);
    cudaGetSymbolAddress((void**)&x0,   g_x0);
    cudaGetSymbolAddress((void**)&gi,   g_gi);
    cudaGetSymbolAddress((void**)&gh,   g_gh);
    cudaGetSymbolAddress((void**)&preW, g_preW);

    const float* hL0 = last_hidden;                 // last_hidden[0]
    const float* hL1 = last_hidden + NB * NH;       // last_hidden[1] (= [-1])

    // 0) repack pre_W into padded/aligned layout (independent; ~1us)
    repack_preW<<<NH, 256>>>(pre_W, preW);

    // 1) u = h_last @ attn_W   (NN: attn_W is [K=H, N=H] row-major)
    gemm_pipe<false><<<dim3(NH / 64, NB / 128, 1), 256>>>(
        hL1, nullptr, attn_W, nullptr, nullptr, nullptr, u, nullptr,
        NB, NH, NH, NH, NH, NH);

    // 2) energies -> softmax -> attn out + context into padded concat buffer
    attn_kernel<<<NB, 256>>>(enc, u, motion, out_attn, cat);

    // 3) rnn_input = cat @ preW_packed^T + pre_b  (K = 1040, fully aligned)
    gemm_pipe<true><<<dim3(NH / 64, NB / 128, 1), 256>>>(
        cat, nullptr, preW, nullptr, pre_b, nullptr, x0, nullptr,
        NB, NH, CAT_LD, CAT_LD, CAT_LD, NH);

    // 4) GRU layer 0: gi and gh batched into one launch (blockIdx.z)
    gemm_pipe<true><<<dim3(3 * NH / 64, NB / 128, 2), 256>>>(
        x0, hL0, Wih0, Whh0, bih0, bhh0, gi, gh,
        NB, 3 * NH, NH, NH, NH, 3 * NH);
    gate_kernel<<<NB * NH / 256, 256>>>(gi, gh, hL0, out_h0);

    // 5) GRU layer 1
    gemm_pipe<true><<<dim3(3 * NH / 64, NB / 128, 2), 256>>>(
        out_h0, hL1, Wih1, Whh1, bih1, bhh1, gi, gh,
        NB, 3 * NH, NH, NH, NH, 3 * NH);
    gate_kernel<<<NB * NH / 256, 256>>>(gi, gh, hL1, out_h1);

    // 6) output = h1 @ post_W^T + post_b
    post_kernel<<<NB, 128>>>(out_h1, post_W, post_b, out_output);
}

// round 4
// speedup vs baseline: 2.2956x; 1.6619x over previous
#include <cuda_runtime.h>
#include <math.h>
#include <stdint.h>

#define NB 512
#define NH 1024
#define NS 64
#define NM 10
#define CAT_LD 1056   // 66 chunks of 16 (K padded, zero-filled)

// ---------------- scratch (device globals; no allocations allowed) ----------
__device__ __align__(1024) float g_u[NB * NH];
__device__ __align__(1024) float g_cat[NB * CAT_LD];
__device__ __align__(1024) float g_x0[NB * NH];
__device__ __align__(1024) float g_gi[NB * 3 * NH];
__device__ __align__(1024) float g_gh[NB * 3 * NH];
__device__ __align__(1024) float g_preW[NH * CAT_LD];
__device__ __align__(1024) float g_Wt[NH * NH];       // attn_W transposed

// ---------------- helpers ----------------------------------------------------
__device__ __forceinline__ uint32_t smem_u32(const void* p) {
    uint32_t a;
    asm("{ .reg .u64 t; cvta.to.shared.u64 t, %1; cvt.u32.u64 %0, t; }"
        : "=r"(a) : "l"(p));
    return a;
}
__device__ __forceinline__ uint32_t tf32_rna(float x) {
    uint32_t r;
    asm("cvt.rna.tf32.f32 %0, %1;" : "=r"(r) : "f"(x));
    return r;
}
__device__ __forceinline__ void mma_tf32(float* c, uint32_t a0, uint32_t a1,
                                         uint32_t a2, uint32_t a3,
                                         uint32_t b0, uint32_t b1) {
    asm volatile(
        "mma.sync.aligned.m16n8k8.row.col.f32.tf32.tf32.f32 "
        "{%0,%1,%2,%3}, {%4,%5,%6,%7}, {%8,%9}, {%0,%1,%2,%3};"
        : "+f"(c[0]), "+f"(c[1]), "+f"(c[2]), "+f"(c[3])
        : "r"(a0), "r"(a1), "r"(a2), "r"(a3), "r"(b0), "r"(b1));
}
__device__ __forceinline__ void cp16(uint32_t dst, const void* src) {
    asm volatile("cp.async.cg.shared.global [%0], [%1], 16;"
                 :: "r"(dst), "l"(src));
}

// ---------------- tf32 warp-MMA GEMM: C[M,N] = A[M,K]*B[N,K]^T + bias -------
// Tile 128x128, 256 thr (8 warps of 64x32), K chunks of 16, 3-stage cp.async.
// SPLIT: 3-product tf32 split (fp32-grade accuracy) for softmax-feeding GEMM.
// blockIdx.z selects problem {A,B,bias,C}.
#define NSTAGE 3
#define STG_F (2 * 128 * 20)              // floats per stage (A + B)
#define DYN_SMEM (NSTAGE * STG_F * 4)     // 61440 B

template <bool SPLIT>
__global__ __launch_bounds__(256, 2) void gemm_mma(
    const float* __restrict__ A0, const float* __restrict__ A1,
    const float* __restrict__ B0, const float* __restrict__ B1,
    const float* __restrict__ bias0, const float* __restrict__ bias1,
    float* __restrict__ C0, float* __restrict__ C1,
    int lda, int ldb, int ldc, int nchunk)
{
    extern __shared__ float dyn[];
    __shared__ float bias_s[128];

    const int tid = threadIdx.x;
    const int wid = tid >> 5, lane = tid & 31;
    const int g = lane >> 2, tg = lane & 3;
    const int wm = wid >> 2, wn = wid & 3;    // warp tile: rows wm*64, cols wn*32
    const int z = blockIdx.z;
    const float* A = z ? A1 : A0;
    const float* B = z ? B1 : B0;
    const float* bias = z ? bias1 : bias0;
    float* C = z ? C1 : C0;
    const int n0 = blockIdx.x * 128;
    const int m0 = blockIdx.y * 128;

    if (tid < 128) bias_s[tid] = bias ? bias[n0 + tid] : 0.f;

    const uint32_t smem_base = smem_u32(dyn);
    // load mapping: 512 segments of 16B per matrix per chunk; 2 per thread
    const int lr0 = tid >> 2,          lk0 = tid & 3;
    const int lr1 = (tid + 256) >> 2,  lk1 = (tid + 256) & 3;

    auto load_chunk = [&](int c, int s) {
        const uint32_t sa = smem_base + s * (STG_F * 4);
        const uint32_t sb = sa + 2560 * 4;
        const float* Ag = A + (size_t)m0 * lda + c * 16;
        const float* Bg = B + (size_t)n0 * ldb + c * 16;
        cp16(sa + (lr0 * 20 + lk0 * 4) * 4, Ag + (size_t)lr0 * lda + lk0 * 4);
        cp16(sa + (lr1 * 20 + lk1 * 4) * 4, Ag + (size_t)lr1 * lda + lk1 * 4);
        cp16(sb + (lr0 * 20 + lk0 * 4) * 4, Bg + (size_t)lr0 * ldb + lk0 * 4);
        cp16(sb + (lr1 * 20 + lk1 * 4) * 4, Bg + (size_t)lr1 * ldb + lk1 * 4);
        asm volatile("cp.async.commit_group;" ::: "memory");
    };

    float acc[4][4][4];
#pragma unroll
    for (int mt = 0; mt < 4; mt++)
#pragma unroll
        for (int nt = 0; nt < 4; nt++)
#pragma unroll
            for (int q = 0; q < 4; q++) acc[mt][nt][q] = 0.f;

#pragma unroll
    for (int s = 0; s < NSTAGE; s++) load_chunk(s, s);

    for (int t = 0; t < nchunk; t++) {
        const int s = t % NSTAGE;
        asm volatile("cp.async.wait_group 2;" ::: "memory");
        __syncthreads();

        const float* As_ = dyn + s * STG_F;
        const float* Bs_ = As_ + 2560;
        const float* ap = As_ + (wm * 64 + g) * 20 + tg;
        const float* bp = Bs_ + (wn * 32 + g) * 20 + tg;

#pragma unroll
        for (int ks = 0; ks < 2; ks++) {
            const int ko = ks * 8;
            if (!SPLIT) {
                uint32_t bf[4][2];
#pragma unroll
                for (int nt = 0; nt < 4; nt++) {
                    bf[nt][0] = tf32_rna(bp[nt * 160 + ko]);
                    bf[nt][1] = tf32_rna(bp[nt * 160 + ko + 4]);
                }
#pragma unroll
                for (int mt = 0; mt < 4; mt++) {
                    uint32_t a0 = tf32_rna(ap[(mt * 16 + 0) * 20 + ko]);
                    uint32_t a1 = tf32_rna(ap[(mt * 16 + 8) * 20 + ko]);
                    uint32_t a2 = tf32_rna(ap[(mt * 16 + 0) * 20 + ko + 4]);
                    uint32_t a3 = tf32_rna(ap[(mt * 16 + 8) * 20 + ko + 4]);
#pragma unroll
                    for (int nt = 0; nt < 4; nt++)
                        mma_tf32(acc[mt][nt], a0, a1, a2, a3, bf[nt][0], bf[nt][1]);
                }
            } else {
                uint32_t bh[4][2], bl[4][2];
#pragma unroll
                for (int nt = 0; nt < 4; nt++) {
#pragma unroll
                    for (int q = 0; q < 2; q++) {
                        float v = bp[nt * 160 + ko + 4 * q];
                        uint32_t hi = tf32_rna(v);
                        bh[nt][q] = hi;
                        bl[nt][q] = tf32_rna(v - __uint_as_float(hi));
                    }
                }
#pragma unroll
                for (int mt = 0; mt < 4; mt++) {
                    float av[4] = {ap[(mt * 16 + 0) * 20 + ko],
                                   ap[(mt * 16 + 8) * 20 + ko],
                                   ap[(mt * 16 + 0) * 20 + ko + 4],
                                   ap[(mt * 16 + 8) * 20 + ko + 4]};
                    uint32_t ah[4], al[4];
#pragma unroll
                    for (int q = 0; q < 4; q++) {
                        ah[q] = tf32_rna(av[q]);
                        al[q] = tf32_rna(av[q] - __uint_as_float(ah[q]));
                    }
#pragma unroll
                    for (int nt = 0; nt < 4; nt++) {
                        mma_tf32(acc[mt][nt], al[0], al[1], al[2], al[3],
                                 bh[nt][0], bh[nt][1]);
                        mma_tf32(acc[mt][nt], ah[0], ah[1], ah[2], ah[3],
                                 bl[nt][0], bl[nt][1]);
                        mma_tf32(acc[mt][nt], ah[0], ah[1], ah[2], ah[3],
                                 bh[nt][0], bh[nt][1]);
                    }
                }
            }
        }
        __syncthreads();
        if (t + NSTAGE < nchunk) load_chunk(t + NSTAGE, s);
    }

    // epilogue
#pragma unroll
    for (int mt = 0; mt < 4; mt++) {
        const int row = m0 + wm * 64 + mt * 16 + g;
        float* Cr0 = C + (size_t)row * ldc + n0;
        float* Cr1 = Cr0 + 8 * ldc;
#pragma unroll
        for (int nt = 0; nt < 4; nt++) {
            const int col = wn * 32 + nt * 8 + tg * 2;
            float2 v0 = make_float2(acc[mt][nt][0] + bias_s[col],
                                    acc[mt][nt][1] + bias_s[col + 1]);
            float2 v1 = make_float2(acc[mt][nt][2] + bias_s[col],
                                    acc[mt][nt][3] + bias_s[col + 1]);
            *(float2*)(Cr0 + col) = v0;
            *(float2*)(Cr1 + col) = v1;
        }
    }
}

// ---------------- attn_W transpose: g_Wt[n][k] = W[k][n] --------------------
__global__ __launch_bounds__(256) void transpose1024(const float* __restrict__ in,
                                                     float* __restrict__ out)
{
    __shared__ float t[32][33];
    int x = blockIdx.x * 32 + threadIdx.x;
    int y0 = blockIdx.y * 32 + threadIdx.y;
#pragma unroll
    for (int j = 0; j < 32; j += 8)
        t[threadIdx.y + j][threadIdx.x] = in[(size_t)(y0 + j) * NH + x];
    __syncthreads();
    x = blockIdx.y * 32 + threadIdx.x;
    y0 = blockIdx.x * 32 + threadIdx.y;
#pragma unroll
    for (int j = 0; j < 32; j += 8)
        out[(size_t)(y0 + j) * NH + x] = t[threadIdx.x][threadIdx.y + j];
}

// ---------------- repack pre_W [1024,1034] -> [1024,1056] zero-padded -------
__global__ __launch_bounds__(256) void repack_preW(const float* __restrict__ W,
                                                   float* __restrict__ out)
{
    const int n = blockIdx.x;
    for (int k = threadIdx.x; k < CAT_LD; k += 256)
        out[(size_t)n * CAT_LD + k] = (k < NH + NM) ? W[(size_t)n * (NH + NM) + k] : 0.f;
}

__device__ __forceinline__ float warp_sum(float v) {
#pragma unroll
    for (int o = 16; o; o >>= 1) v += __shfl_xor_sync(0xffffffffu, v, o);
    return v;
}

// ---------------- attention: energies + softmax + context + concat ----------
__global__ __launch_bounds__(256) void attn_kernel(
    const float* __restrict__ enc, const float* __restrict__ u,
    const float* __restrict__ motion, float* __restrict__ attn_out,
    float* __restrict__ cat)
{
    const int b = blockIdx.x;
    const int tid = threadIdx.x;
    const int lane = tid & 31, warp = tid >> 5;
    __shared__ float e[NS];

    float ureg[32];
    const float* ub = u + (size_t)b * NH;
#pragma unroll
    for (int i = 0; i < 32; i++) ureg[i] = ub[i * 32 + lane];

    for (int s = warp; s < NS; s += 8) {
        const float* ep = enc + ((size_t)s * NB + b) * NH;
        float acc = 0.f;
#pragma unroll
        for (int i = 0; i < 32; i++) acc = fmaf(ep[i * 32 + lane], ureg[i], acc);
        acc = warp_sum(acc);
        if (lane == 0) e[s] = acc;
    }
    __syncthreads();

    if (tid < 32) {
        float v0 = e[tid], v1 = e[tid + 32];
        float m = fmaxf(v0, v1);
#pragma unroll
        for (int o = 16; o; o >>= 1) m = fmaxf(m, __shfl_xor_sync(0xffffffffu, m, o));
        float e0 = expf(v0 - m), e1 = expf(v1 - m);
        float s = warp_sum(e0 + e1);
        float inv = 1.f / s;
        e[tid] = e0 * inv;
        e[tid + 32] = e1 * inv;
    }
    __syncthreads();

    if (tid < NS) attn_out[(size_t)b * NS + tid] = e[tid];
    if (tid < NM) cat[(size_t)b * CAT_LD + tid] = motion[(size_t)b * NM + tid];
    if (tid < CAT_LD - NH - NM)
        cat[(size_t)b * CAT_LD + NH + NM + tid] = 0.f;   // zero pad 1034..1055

#pragma unroll
    for (int j = 0; j < 4; j++) {
        const int h = tid + j * 256;
        float acc = 0.f;
#pragma unroll 8
        for (int s = 0; s < NS; s++)
            acc = fmaf(e[s], enc[((size_t)s * NB + b) * NH + h], acc);
        cat[(size_t)b * CAT_LD + NM + h] = acc;
    }
}

// ---------------- GRU gate pointwise ----------------------------------------
__global__ __launch_bounds__(256) void gate_kernel(
    const float* __restrict__ gi, const float* __restrict__ gh,
    const float* __restrict__ hprev, float* __restrict__ out_h)
{
    const int idx = blockIdx.x * blockDim.x + threadIdx.x;
    const int b = idx >> 10, n = idx & (NH - 1);
    const float* gib = gi + (size_t)b * 3 * NH;
    const float* ghb = gh + (size_t)b * 3 * NH;
    float ir = gib[n], iz = gib[NH + n], inn = gib[2 * NH + n];
    float hr = ghb[n], hz = ghb[NH + n], hn = ghb[2 * NH + n];
    float r = 1.f / (1.f + expf(-(ir + hr)));
    float z = 1.f / (1.f + expf(-(iz + hz)));
    float nn = tanhf(inn + r * hn);
    out_h[idx] = (1.f - z) * nn + z * hprev[idx];
}

// ---------------- post linear: [B,1024] -> [B,10] ---------------------------
__global__ __launch_bounds__(128) void post_kernel(
    const float* __restrict__ h1, const float* __restrict__ W,
    const float* __restrict__ bias, float* __restrict__ out)
{
    const int b = blockIdx.x;
    const int tid = threadIdx.x;
    float acc[10];
#pragma unroll
    for (int o = 0; o < 10; o++) acc[o] = 0.f;
    for (int h = tid; h < NH; h += 128) {
        float x = h1[(size_t)b * NH + h];
#pragma unroll
        for (int o = 0; o < 10; o++) acc[o] = fmaf(x, W[(size_t)o * NH + h], acc[o]);
    }
    __shared__ float red[128];
#pragma unroll
    for (int o = 0; o < 10; o++) {
        red[tid] = acc[o];
        __syncthreads();
        for (int st = 64; st; st >>= 1) {
            if (tid < st) red[tid] += red[tid + st];
            __syncthreads();
        }
        if (tid == 0) out[(size_t)b * 10 + o] = red[0] + bias[o];
        __syncthreads();
    }
}

// ---------------- host launch ------------------------------------------------
extern "C" void kernel_launch(void* const* d_in, const int* in_sizes, int n_in,
                              void* d_out, int out_size)
{
    const float* motion      = (const float*)d_in[0];
    const float* last_hidden = (const float*)d_in[1];
    const float* enc         = (const float*)d_in[2];
    const float* attn_W      = (const float*)d_in[3];
    /* d_in[4] = attn_b: unused (softmax shift-invariant) */
    const float* pre_W  = (const float*)d_in[5];
    const float* pre_b  = (const float*)d_in[6];
    const float* Wih0   = (const float*)d_in[7];
    const float* Whh0   = (const float*)d_in[8];
    const float* bih0   = (const float*)d_in[9];
    const float* bhh0   = (const float*)d_in[10];
    const float* Wih1   = (const float*)d_in[11];
    const float* Whh1   = (const float*)d_in[12];
    const float* bih1   = (const float*)d_in[13];
    const float* bhh1   = (const float*)d_in[14];
    const float* post_W = (const float*)d_in[15];
    const float* post_b = (const float*)d_in[16];

    float* out        = (float*)d_out;
    float* out_output = out;
    float* out_h0     = out + NB * 10;
    float* out_h1     = out + NB * 10 + NB * NH;
    float* out_attn   = out + NB * 10 + 2 * NB * NH;

    float *u, *cat, *x0, *gi, *gh, *preW, *Wt;
    cudaGetSymbolAddress((void**)&u,    g_u);
    cudaGetSymbolAddress((void**)&cat,  g_cat);
    cudaGetSymbolAddress((void**)&x0,   g_x0);
    cudaGetSymbolAddress((void**)&gi,   g_gi);
    cudaGetSymbolAddress((void**)&gh,   g_gh);
    cudaGetSymbolAddress((void**)&preW, g_preW);
    cudaGetSymbolAddress((void**)&Wt,   g_Wt);

    const float* hL0 = last_hidden;
    const float* hL1 = last_hidden + NB * NH;

    cudaFuncSetAttribute(gemm_mma<false>,
                         cudaFuncAttributeMaxDynamicSharedMemorySize, DYN_SMEM);
    cudaFuncSetAttribute(gemm_mma<true>,
                         cudaFuncAttributeMaxDynamicSharedMemorySize, DYN_SMEM);

    // 0) weight repacks (independent, ~2-3us)
    transpose1024<<<dim3(32, 32), dim3(32, 8)>>>(attn_W, Wt);
    repack_preW<<<NH, 256>>>(pre_W, preW);

    // 1) u = hL1 @ attn_W  (split-tf32: feeds softmax logits, needs fp32 grade)
    gemm_mma<true><<<dim3(8, 4, 1), 256, DYN_SMEM>>>(
        hL1, nullptr, Wt, nullptr, nullptr, nullptr, u, nullptr,
        NH, NH, NH, 64);

    // 2) energies -> softmax -> attn out + context into padded concat buffer
    attn_kernel<<<NB, 256>>>(enc, u, motion, out_attn, cat);

    // 3) rnn_input = cat @ preW^T + pre_b   (K = 1056 zero-padded)
    gemm_mma<false><<<dim3(8, 4, 1), 256, DYN_SMEM>>>(
        cat, nullptr, preW, nullptr, pre_b, nullptr, x0, nullptr,
        CAT_LD, CAT_LD, NH, 66);

    // 4) GRU layer 0: gi | gh batched via blockIdx.z
    gemm_mma<false><<<dim3(24, 4, 2), 256, DYN_SMEM>>>(
        x0, hL0, Wih0, Whh0, bih0, bhh0, gi, gh,
        NH, NH, 3 * NH, 64);
    gate_kernel<<<NB * NH / 256, 256>>>(gi, gh, hL0, out_h0);

    // 5) GRU layer 1
    gemm_mma<false><<<dim3(24, 4, 2), 256, DYN_SMEM>>>(
        out_h0, hL1, Wih1, Whh1, bih1, bhh1, gi, gh,
        NH, NH, 3 * NH, 64);
    gate_kernel<<<NB * NH / 256, 256>>>(gi, gh, hL1, out_h1);

    // 6) output = h1 @ post_W^T + post_b
    post_kernel<<<NB, 128>>>(out_h1, post_W, post_b, out_output);
}

// round 5
// speedup vs baseline: 2.4496x; 1.0671x over previous
#include <cuda_runtime.h>
#include <math.h>
#include <stdint.h>

#define NB 512
#define NH 1024
#define NS 64
#define NM 10
#define CAT_LD 1056   // 66 chunks of 16 (K padded, zero-filled)

// ---------------- scratch (device globals; no allocations allowed) ----------
__device__ __align__(1024) float g_u[NB * NH];
__device__ __align__(1024) float g_cat[NB * CAT_LD];
__device__ __align__(1024) float g_x0[NB * NH];
__device__ __align__(1024) float g_gi[NB * 3 * NH];
__device__ __align__(1024) float g_gh[NB * 3 * NH];
__device__ __align__(1024) float g_preW[NH * CAT_LD];
__device__ __align__(1024) float g_Wt[NH * NH];       // attn_W transposed

// ---------------- helpers ----------------------------------------------------
__device__ __forceinline__ uint32_t smem_u32(const void* p) {
    uint32_t a;
    asm("{ .reg .u64 t; cvta.to.shared.u64 t, %1; cvt.u32.u64 %0, t; }"
        : "=r"(a) : "l"(p));
    return a;
}
__device__ __forceinline__ uint32_t tf32_rna(float x) {
    uint32_t r;
    asm("cvt.rna.tf32.f32 %0, %1;" : "=r"(r) : "f"(x));
    return r;
}
__device__ __forceinline__ void mma_tf32(float* c, uint32_t a0, uint32_t a1,
                                         uint32_t a2, uint32_t a3,
                                         uint32_t b0, uint32_t b1) {
    asm volatile(
        "mma.sync.aligned.m16n8k8.row.col.f32.tf32.tf32.f32 "
        "{%0,%1,%2,%3}, {%4,%5,%6,%7}, {%8,%9}, {%0,%1,%2,%3};"
        : "+f"(c[0]), "+f"(c[1]), "+f"(c[2]), "+f"(c[3])
        : "r"(a0), "r"(a1), "r"(a2), "r"(a3), "r"(b0), "r"(b1));
}
__device__ __forceinline__ void cp16(uint32_t dst, const void* src) {
    asm volatile("cp.async.cg.shared.global [%0], [%1], 16;"
                 :: "r"(dst), "l"(src));
}

// ---------------- tf32 warp-MMA GEMM: C[M,N] = A[M,K]*B[N,K]^T + bias -------
// Tile 128x128, 256 thr (8 warps of 64x32), K chunks of 16, 3-stage cp.async.
// Non-SPLIT: raw fp32 bits fed to mma (HW truncation) -> no cvt in inner loop.
// SPLIT: 3-product tf32 split (fp32-grade) for the softmax-feeding GEMM.
#define NSTAGE 3
#define STG_F (2 * 128 * 20)              // floats per stage (A + B)
#define DYN_SMEM (NSTAGE * STG_F * 4)     // 61440 B

template <bool SPLIT>
__global__ __launch_bounds__(256, 2) void gemm_mma(
    const float* __restrict__ A0, const float* __restrict__ A1,
    const float* __restrict__ B0, const float* __restrict__ B1,
    const float* __restrict__ bias0, const float* __restrict__ bias1,
    float* __restrict__ C0, float* __restrict__ C1,
    int lda, int ldb, int ldc, int nchunk)
{
    extern __shared__ float dyn[];
    __shared__ float bias_s[128];

    const int tid = threadIdx.x;
    const int wid = tid >> 5, lane = tid & 31;
    const int g = lane >> 2, tg = lane & 3;
    const int wm = wid >> 2, wn = wid & 3;
    const int z = blockIdx.z;
    const float* A = z ? A1 : A0;
    const float* B = z ? B1 : B0;
    const float* bias = z ? bias1 : bias0;
    float* C = z ? C1 : C0;
    const int n0 = blockIdx.x * 128;
    const int m0 = blockIdx.y * 128;

    if (tid < 128) bias_s[tid] = bias ? bias[n0 + tid] : 0.f;

    const uint32_t smem_base = smem_u32(dyn);
    const int lr0 = tid >> 2,          lk0 = tid & 3;
    const int lr1 = (tid + 256) >> 2,  lk1 = (tid + 256) & 3;

    auto load_chunk = [&](int c, int s) {
        const uint32_t sa = smem_base + s * (STG_F * 4);
        const uint32_t sb = sa + 2560 * 4;
        const float* Ag = A + (size_t)m0 * lda + c * 16;
        const float* Bg = B + (size_t)n0 * ldb + c * 16;
        cp16(sa + (lr0 * 20 + lk0 * 4) * 4, Ag + (size_t)lr0 * lda + lk0 * 4);
        cp16(sa + (lr1 * 20 + lk1 * 4) * 4, Ag + (size_t)lr1 * lda + lk1 * 4);
        cp16(sb + (lr0 * 20 + lk0 * 4) * 4, Bg + (size_t)lr0 * ldb + lk0 * 4);
        cp16(sb + (lr1 * 20 + lk1 * 4) * 4, Bg + (size_t)lr1 * ldb + lk1 * 4);
        asm volatile("cp.async.commit_group;" ::: "memory");
    };

    float acc[4][4][4];
#pragma unroll
    for (int mt = 0; mt < 4; mt++)
#pragma unroll
        for (int nt = 0; nt < 4; nt++)
#pragma unroll
            for (int q = 0; q < 4; q++) acc[mt][nt][q] = 0.f;

#pragma unroll
    for (int s = 0; s < NSTAGE; s++) load_chunk(s, s);

    for (int t = 0; t < nchunk; t++) {
        const int s = t % NSTAGE;
        asm volatile("cp.async.wait_group 2;" ::: "memory");
        __syncthreads();

        const float* As_ = dyn + s * STG_F;
        const float* Bs_ = As_ + 2560;
        const float* ap = As_ + (wm * 64 + g) * 20 + tg;
        const float* bp = Bs_ + (wn * 32 + g) * 20 + tg;

#pragma unroll
        for (int ks = 0; ks < 2; ks++) {
            const int ko = ks * 8;
            if (!SPLIT) {
                uint32_t bf[4][2];
#pragma unroll
                for (int nt = 0; nt < 4; nt++) {
                    bf[nt][0] = __float_as_uint(bp[nt * 160 + ko]);
                    bf[nt][1] = __float_as_uint(bp[nt * 160 + ko + 4]);
                }
#pragma unroll
                for (int mt = 0; mt < 4; mt++) {
                    uint32_t a0 = __float_as_uint(ap[(mt * 16 + 0) * 20 + ko]);
                    uint32_t a1 = __float_as_uint(ap[(mt * 16 + 8) * 20 + ko]);
                    uint32_t a2 = __float_as_uint(ap[(mt * 16 + 0) * 20 + ko + 4]);
                    uint32_t a3 = __float_as_uint(ap[(mt * 16 + 8) * 20 + ko + 4]);
#pragma unroll
                    for (int nt = 0; nt < 4; nt++)
                        mma_tf32(acc[mt][nt], a0, a1, a2, a3, bf[nt][0], bf[nt][1]);
                }
            } else {
                uint32_t bh[4][2], bl[4][2];
#pragma unroll
                for (int nt = 0; nt < 4; nt++) {
#pragma unroll
                    for (int q = 0; q < 2; q++) {
                        float v = bp[nt * 160 + ko + 4 * q];
                        uint32_t hi = tf32_rna(v);
                        bh[nt][q] = hi;
                        bl[nt][q] = tf32_rna(v - __uint_as_float(hi));
                    }
                }
#pragma unroll
                for (int mt = 0; mt < 4; mt++) {
                    float av[4] = {ap[(mt * 16 + 0) * 20 + ko],
                                   ap[(mt * 16 + 8) * 20 + ko],
                                   ap[(mt * 16 + 0) * 20 + ko + 4],
                                   ap[(mt * 16 + 8) * 20 + ko + 4]};
                    uint32_t ah[4], al[4];
#pragma unroll
                    for (int q = 0; q < 4; q++) {
                        ah[q] = tf32_rna(av[q]);
                        al[q] = tf32_rna(av[q] - __uint_as_float(ah[q]));
                    }
#pragma unroll
                    for (int nt = 0; nt < 4; nt++) {
                        mma_tf32(acc[mt][nt], al[0], al[1], al[2], al[3],
                                 bh[nt][0], bh[nt][1]);
                        mma_tf32(acc[mt][nt], ah[0], ah[1], ah[2], ah[3],
                                 bl[nt][0], bl[nt][1]);
                        mma_tf32(acc[mt][nt], ah[0], ah[1], ah[2], ah[3],
                                 bh[nt][0], bh[nt][1]);
                    }
                }
            }
        }
        __syncthreads();
        if (t + NSTAGE < nchunk) load_chunk(t + NSTAGE, s);
    }

#pragma unroll
    for (int mt = 0; mt < 4; mt++) {
        const int row = m0 + wm * 64 + mt * 16 + g;
        float* Cr0 = C + (size_t)row * ldc + n0;
        float* Cr1 = Cr0 + 8 * ldc;
#pragma unroll
        for (int nt = 0; nt < 4; nt++) {
            const int col = wn * 32 + nt * 8 + tg * 2;
            float2 v0 = make_float2(acc[mt][nt][0] + bias_s[col],
                                    acc[mt][nt][1] + bias_s[col + 1]);
            float2 v1 = make_float2(acc[mt][nt][2] + bias_s[col],
                                    acc[mt][nt][3] + bias_s[col + 1]);
            *(float2*)(Cr0 + col) = v0;
            *(float2*)(Cr1 + col) = v1;
        }
    }
}

// ---------------- attn_W transpose -------------------------------------------
__global__ __launch_bounds__(256) void transpose1024(const float* __restrict__ in,
                                                     float* __restrict__ out)
{
    __shared__ float t[32][33];
    int x = blockIdx.x * 32 + threadIdx.x;
    int y0 = blockIdx.y * 32 + threadIdx.y;
#pragma unroll
    for (int j = 0; j < 32; j += 8)
        t[threadIdx.y + j][threadIdx.x] = in[(size_t)(y0 + j) * NH + x];
    __syncthreads();
    x = blockIdx.y * 32 + threadIdx.x;
    y0 = blockIdx.x * 32 + threadIdx.y;
#pragma unroll
    for (int j = 0; j < 32; j += 8)
        out[(size_t)(y0 + j) * NH + x] = t[threadIdx.x][threadIdx.y + j];
}

// ---------------- repack pre_W [1024,1034] -> [1024,1056] zero-padded -------
__global__ __launch_bounds__(256) void repack_preW(const float* __restrict__ W,
                                                   float* __restrict__ out)
{
    const int n = blockIdx.x;
    for (int k = threadIdx.x; k < CAT_LD; k += 256)
        out[(size_t)n * CAT_LD + k] = (k < NH + NM) ? W[(size_t)n * (NH + NM) + k] : 0.f;
}

__device__ __forceinline__ float warp_sum(float v) {
#pragma unroll
    for (int o = 16; o; o >>= 1) v += __shfl_xor_sync(0xffffffffu, v, o);
    return v;
}

// ---------------- fused single-pass attention (online softmax) --------------
// One block per batch row b; 8 warps x 8 s-rows. Each enc row is read ONCE:
// dot with u -> e_s, then the register-resident row is accumulated into a
// per-warp context with flash-style running max/sum rescaling. Warps merge
// via smem at the end; exact softmax weights recovered from raw e_s.
__global__ __launch_bounds__(256, 2) void attn_fused(
    const float* __restrict__ enc, const float* __restrict__ u,
    const float* __restrict__ motion, float* __restrict__ attn_out,
    float* __restrict__ cat)
{
    const int b = blockIdx.x;
    const int tid = threadIdx.x;
    const int lane = tid & 31, w = tid >> 5;

    __shared__ float e_raw[NS];
    __shared__ float warp_m[8], warp_z[8];
    __shared__ __align__(16) float ctxs[8 * NH];

    const float4* u4 = (const float4*)(u + (size_t)b * NH);
    float4 ur[8];
#pragma unroll
    for (int i = 0; i < 8; i++) ur[i] = u4[i * 32 + lane];

    float4 cacc[8];
#pragma unroll
    for (int i = 0; i < 8; i++) cacc[i] = make_float4(0.f, 0.f, 0.f, 0.f);
    float m = -1e30f, Z = 0.f;

#pragma unroll
    for (int si = 0; si < 8; si++) {
        const int s = w + si * 8;
        const float4* ep = (const float4*)(enc + ((size_t)s * NB + b) * NH);
        float4 row[8];
        float d = 0.f;
#pragma unroll
        for (int i = 0; i < 8; i++) {
            row[i] = ep[i * 32 + lane];
            d = fmaf(row[i].x, ur[i].x, d);
            d = fmaf(row[i].y, ur[i].y, d);
            d = fmaf(row[i].z, ur[i].z, d);
            d = fmaf(row[i].w, ur[i].w, d);
        }
        d = warp_sum(d);
        if (lane == 0) e_raw[s] = d;
        const float mn = fmaxf(m, d);
        const float scale = __expf(m - mn);
        const float wgt = __expf(d - mn);
        Z = Z * scale + wgt;
#pragma unroll
        for (int i = 0; i < 8; i++) {
            cacc[i].x = fmaf(cacc[i].x, scale, wgt * row[i].x);
            cacc[i].y = fmaf(cacc[i].y, scale, wgt * row[i].y);
            cacc[i].z = fmaf(cacc[i].z, scale, wgt * row[i].z);
            cacc[i].w = fmaf(cacc[i].w, scale, wgt * row[i].w);
        }
        m = mn;
    }

    if (lane == 0) { warp_m[w] = m; warp_z[w] = Z; }
    float4* cs = (float4*)(ctxs + w * NH);
#pragma unroll
    for (int i = 0; i < 8; i++) cs[i * 32 + lane] = cacc[i];
    __syncthreads();

    float gm = warp_m[0];
#pragma unroll
    for (int ww = 1; ww < 8; ww++) gm = fmaxf(gm, warp_m[ww]);
    float gZ = 0.f;
#pragma unroll
    for (int ww = 0; ww < 8; ww++) gZ += warp_z[ww] * __expf(warp_m[ww] - gm);
    const float invZ = 1.f / gZ;

    if (tid < NS) attn_out[(size_t)b * NS + tid] = __expf(e_raw[tid] - gm) * invZ;
    if (tid < NM) cat[(size_t)b * CAT_LD + tid] = motion[(size_t)b * NM + tid];
    if (tid < CAT_LD - NH - NM)
        cat[(size_t)b * CAT_LD + NH + NM + tid] = 0.f;

    // combine 8 warp contexts for h = tid*4 .. tid*4+3
    float4 a = make_float4(0.f, 0.f, 0.f, 0.f);
#pragma unroll
    for (int ww = 0; ww < 8; ww++) {
        const float sc = __expf(warp_m[ww] - gm);
        float4 v = *(const float4*)&ctxs[ww * NH + tid * 4];
        a.x = fmaf(v.x, sc, a.x);
        a.y = fmaf(v.y, sc, a.y);
        a.z = fmaf(v.z, sc, a.z);
        a.w = fmaf(v.w, sc, a.w);
    }
    float* cp = cat + (size_t)b * CAT_LD + NM + tid * 4;
    *(float2*)cp       = make_float2(a.x * invZ, a.y * invZ);
    *(float2*)(cp + 2) = make_float2(a.z * invZ, a.w * invZ);
}

// ---------------- GRU gate pointwise ----------------------------------------
__global__ __launch_bounds__(256) void gate_kernel(
    const float* __restrict__ gi, const float* __restrict__ gh,
    const float* __restrict__ hprev, float* __restrict__ out_h)
{
    const int idx = blockIdx.x * blockDim.x + threadIdx.x;
    const int b = idx >> 10, n = idx & (NH - 1);
    const float* gib = gi + (size_t)b * 3 * NH;
    const float* ghb = gh + (size_t)b * 3 * NH;
    float ir = gib[n], iz = gib[NH + n], inn = gib[2 * NH + n];
    float hr = ghb[n], hz = ghb[NH + n], hn = ghb[2 * NH + n];
    float r = 1.f / (1.f + expf(-(ir + hr)));
    float z = 1.f / (1.f + expf(-(iz + hz)));
    float nn = tanhf(inn + r * hn);
    out_h[idx] = (1.f - z) * nn + z * hprev[idx];
}

// ---------------- post linear: [B,1024] -> [B,10] ---------------------------
__global__ __launch_bounds__(128) void post_kernel(
    const float* __restrict__ h1, const float* __restrict__ W,
    const float* __restrict__ bias, float* __restrict__ out)
{
    const int b = blockIdx.x;
    const int tid = threadIdx.x;
    float acc[10];
#pragma unroll
    for (int o = 0; o < 10; o++) acc[o] = 0.f;
    for (int h = tid; h < NH; h += 128) {
        float x = h1[(size_t)b * NH + h];
#pragma unroll
        for (int o = 0; o < 10; o++) acc[o] = fmaf(x, W[(size_t)o * NH + h], acc[o]);
    }
    __shared__ float red[128];
#pragma unroll
    for (int o = 0; o < 10; o++) {
        red[tid] = acc[o];
        __syncthreads();
        for (int st = 64; st; st >>= 1) {
            if (tid < st) red[tid] += red[tid + st];
            __syncthreads();
        }
        if (tid == 0) out[(size_t)b * 10 + o] = red[0] + bias[o];
        __syncthreads();
    }
}

// ---------------- host launch ------------------------------------------------
extern "C" void kernel_launch(void* const* d_in, const int* in_sizes, int n_in,
                              void* d_out, int out_size)
{
    const float* motion      = (const float*)d_in[0];
    const float* last_hidden = (const float*)d_in[1];
    const float* enc         = (const float*)d_in[2];
    const float* attn_W      = (const float*)d_in[3];
    /* d_in[4] = attn_b: unused (softmax shift-invariant) */
    const float* pre_W  = (const float*)d_in[5];
    const float* pre_b  = (const float*)d_in[6];
    const float* Wih0   = (const float*)d_in[7];
    const float* Whh0   = (const float*)d_in[8];
    const float* bih0   = (const float*)d_in[9];
    const float* bhh0   = (const float*)d_in[10];
    const float* Wih1   = (const float*)d_in[11];
    const float* Whh1   = (const float*)d_in[12];
    const float* bih1   = (const float*)d_in[13];
    const float* bhh1   = (const float*)d_in[14];
    const float* post_W = (const float*)d_in[15];
    const float* post_b = (const float*)d_in[16];

    float* out        = (float*)d_out;
    float* out_output = out;
    float* out_h0     = out + NB * 10;
    float* out_h1     = out + NB * 10 + NB * NH;
    float* out_attn   = out + NB * 10 + 2 * NB * NH;

    float *u, *cat, *x0, *gi, *gh, *preW, *Wt;
    cudaGetSymbolAddress((void**)&u,    g_u);
    cudaGetSymbolAddress((void**)&cat,  g_cat);
    cudaGetSymbolAddress((void**)&x0,   g_x0);
    cudaGetSymbolAddress((void**)&gi,   g_gi);
    cudaGetSymbolAddress((void**)&gh,   g_gh);
    cudaGetSymbolAddress((void**)&preW, g_preW);
    cudaGetSymbolAddress((void**)&Wt,   g_Wt);

    const float* hL0 = last_hidden;
    const float* hL1 = last_hidden + NB * NH;

    cudaFuncSetAttribute(gemm_mma<false>,
                         cudaFuncAttributeMaxDynamicSharedMemorySize, DYN_SMEM);
    cudaFuncSetAttribute(gemm_mma<true>,
                         cudaFuncAttributeMaxDynamicSharedMemorySize, DYN_SMEM);

    // 0) weight repacks (independent, ~2-3us)
    transpose1024<<<dim3(32, 32), dim3(32, 8)>>>(attn_W, Wt);
    repack_preW<<<NH, 256>>>(pre_W, preW);

    // 1) u = hL1 @ attn_W  (split-tf32: feeds softmax logits, needs fp32 grade)
    gemm_mma<true><<<dim3(8, 4, 1), 256, DYN_SMEM>>>(
        hL1, nullptr, Wt, nullptr, nullptr, nullptr, u, nullptr,
        NH, NH, NH, 64);

    // 2) fused single-pass attention (enc read once)
    attn_fused<<<NB, 256>>>(enc, u, motion, out_attn, cat);

    // 3) rnn_input = cat @ preW^T + pre_b   (K = 1056 zero-padded)
    gemm_mma<false><<<dim3(8, 4, 1), 256, DYN_SMEM>>>(
        cat, nullptr, preW, nullptr, pre_b, nullptr, x0, nullptr,
        CAT_LD, CAT_LD, NH, 66);

    // 4) GRU layer 0: gi | gh batched via blockIdx.z
    gemm_mma<false><<<dim3(24, 4, 2), 256, DYN_SMEM>>>(
        x0, hL0, Wih0, Whh0, bih0, bhh0, gi, gh,
        NH, NH, 3 * NH, 64);
    gate_kernel<<<NB * NH / 256, 256>>>(gi, gh, hL0, out_h0);

    // 5) GRU layer 1
    gemm_mma<false><<<dim3(24, 4, 2), 256, DYN_SMEM>>>(
        out_h0, hL1, Wih1, Whh1, bih1, bhh1, gi, gh,
        NH, NH, 3 * NH, 64);
    gate_kernel<<<NB * NH / 256, 256>>>(gi, gh, hL1, out_h1);

    // 6) output = h1 @ post_W^T + post_b
    post_kernel<<<NB, 128>>>(out_h1, post_W, post_b, out_output);
}

// round 6
// speedup vs baseline: 2.8058x; 1.1454x over previous
#include <cuda_runtime.h>
#include <math.h>
#include <stdint.h>

#define NB 512
#define NH 1024
#define NS 64
#define NM 10
#define CAT_LD 1056   // 66 chunks of 16 (K padded, zero-filled)
#define NJOBS 6

// ---------------- scratch (device globals; no allocations allowed) ----------
__device__ __align__(1024) float g_u[NB * NH];
__device__ __align__(1024) float g_upart[4 * NB * NH];
__device__ __align__(1024) float g_cat[NB * CAT_LD];
__device__ __align__(1024) float g_x0[NB * NH];
__device__ __align__(1024) float g_gi[NB * 3 * NH];
__device__ __align__(1024) float g_gh0[NB * 3 * NH];
__device__ __align__(1024) float g_gh1[NB * 3 * NH];
__device__ __align__(1024) float g_preW[NH * CAT_LD];
__device__ __align__(1024) float g_Wt[NH * NH];       // attn_W transposed

struct Jobs {
    const float* A[NJOBS]; const float* B[NJOBS];
    const float* bias[NJOBS]; float* C[NJOBS];
    int lda[NJOBS], ldb[NJOBS], ldc[NJOBS], nchunk[NJOBS], nx[NJOBS], split[NJOBS];
};

// ---------------- helpers ----------------------------------------------------
__device__ __forceinline__ uint32_t smem_u32(const void* p) {
    uint32_t a;
    asm("{ .reg .u64 t; cvta.to.shared.u64 t, %1; cvt.u32.u64 %0, t; }"
        : "=r"(a) : "l"(p));
    return a;
}
__device__ __forceinline__ uint32_t tf32_rna(float x) {
    uint32_t r;
    asm("cvt.rna.tf32.f32 %0, %1;" : "=r"(r) : "f"(x));
    return r;
}
__device__ __forceinline__ void mma_tf32(float* c, uint32_t a0, uint32_t a1,
                                         uint32_t a2, uint32_t a3,
                                         uint32_t b0, uint32_t b1) {
    asm volatile(
        "mma.sync.aligned.m16n8k8.row.col.f32.tf32.tf32.f32 "
        "{%0,%1,%2,%3}, {%4,%5,%6,%7}, {%8,%9}, {%0,%1,%2,%3};"
        : "+f"(c[0]), "+f"(c[1]), "+f"(c[2]), "+f"(c[3])
        : "r"(a0), "r"(a1), "r"(a2), "r"(a3), "r"(b0), "r"(b1));
}
__device__ __forceinline__ void cp16(uint32_t dst, const void* src) {
    asm volatile("cp.async.cg.shared.global [%0], [%1], 16;"
                 :: "r"(dst), "l"(src));
}
__device__ __forceinline__ void ldsm4(uint32_t& r0, uint32_t& r1, uint32_t& r2,
                                      uint32_t& r3, uint32_t addr) {
    asm volatile("ldmatrix.sync.aligned.m8n8.x4.shared.b16 {%0,%1,%2,%3}, [%4];"
                 : "=r"(r0), "=r"(r1), "=r"(r2), "=r"(r3) : "r"(addr));
}

// ---------------- tf32 warp-MMA GEMM: C[M,N] = A[M,K]*B[N,K]^T + bias -------
// Tile 128x128, 8 warps (64x32 each), K chunks of 16, 3-stage cp.async,
// ldmatrix fragment loads. blockIdx.z indexes an entry of the job table
// (early-exit when blockIdx.x >= nx). split=1 -> 3-product tf32 split.
#define NSTAGE 3
#define STG_F (2 * 128 * 20)
#define DYN_SMEM (NSTAGE * STG_F * 4)     // 61440 B

__global__ __launch_bounds__(256, 2) void gemm_mma(Jobs jobs)
{
    const int z = blockIdx.z;
    if (blockIdx.x >= jobs.nx[z]) return;

    extern __shared__ float dyn[];
    __shared__ float bias_s[128];

    const float* A = jobs.A[z];
    const float* B = jobs.B[z];
    const float* bias = jobs.bias[z];
    float* C = jobs.C[z];
    const int lda = jobs.lda[z], ldb = jobs.ldb[z], ldc = jobs.ldc[z];
    const int nchunk = jobs.nchunk[z], split = jobs.split[z];

    const int tid = threadIdx.x;
    const int wid = tid >> 5, lane = tid & 31;
    const int g = lane >> 2, tg = lane & 3;
    const int wm = wid >> 2, wn = wid & 3;
    const int lr = lane & 7, lq = lane >> 3;
    const int n0 = blockIdx.x * 128;
    const int m0 = blockIdx.y * 128;

    if (tid < 128) bias_s[tid] = bias ? bias[n0 + tid] : 0.f;

    const uint32_t smem_base = smem_u32(dyn);
    // ldmatrix per-lane byte offsets within a stage
    const uint32_t a_off = (uint32_t)(((wm * 64 + (lq & 1) * 8 + lr) * 20 +
                                      (lq >> 1) * 4) * 4);
    const uint32_t b_off = (uint32_t)((2560 + (wn * 32 + (lq >> 1) * 8 + lr) * 20 +
                                      (lq & 1) * 4) * 4);

    const int lr0 = tid >> 2,          lk0 = tid & 3;
    const int lr1 = (tid + 256) >> 2,  lk1 = (tid + 256) & 3;

    auto load_chunk = [&](int c, int s) {
        const uint32_t sa = smem_base + s * (STG_F * 4);
        const uint32_t sb = sa + 2560 * 4;
        const float* Ag = A + (size_t)m0 * lda + c * 16;
        const float* Bg = B + (size_t)n0 * ldb + c * 16;
        cp16(sa + (lr0 * 20 + lk0 * 4) * 4, Ag + (size_t)lr0 * lda + lk0 * 4);
        cp16(sa + (lr1 * 20 + lk1 * 4) * 4, Ag + (size_t)lr1 * lda + lk1 * 4);
        cp16(sb + (lr0 * 20 + lk0 * 4) * 4, Bg + (size_t)lr0 * ldb + lk0 * 4);
        cp16(sb + (lr1 * 20 + lk1 * 4) * 4, Bg + (size_t)lr1 * ldb + lk1 * 4);
        asm volatile("cp.async.commit_group;" ::: "memory");
    };

    float acc[4][4][4];
#pragma unroll
    for (int mt = 0; mt < 4; mt++)
#pragma unroll
        for (int nt = 0; nt < 4; nt++)
#pragma unroll
            for (int q = 0; q < 4; q++) acc[mt][nt][q] = 0.f;

#pragma unroll
    for (int s = 0; s < NSTAGE; s++) load_chunk(s, s);

    for (int t = 0; t < nchunk; t++) {
        const int s = t % NSTAGE;
        asm volatile("cp.async.wait_group 2;" ::: "memory");
        __syncthreads();

        const uint32_t sbase = smem_base + s * (STG_F * 4);
        const uint32_t abase = sbase + a_off;
        const uint32_t bbase = sbase + b_off;

#pragma unroll
        for (int ks = 0; ks < 2; ks++) {
            uint32_t au[4][4], bu[4][2];
#pragma unroll
            for (int mt = 0; mt < 4; mt++)
                ldsm4(au[mt][0], au[mt][1], au[mt][2], au[mt][3],
                      abase + mt * 1280 + ks * 32);
#pragma unroll
            for (int j = 0; j < 2; j++)
                ldsm4(bu[2 * j][0], bu[2 * j][1], bu[2 * j + 1][0],
                      bu[2 * j + 1][1], bbase + j * 1280 + ks * 32);

            if (!split) {
#pragma unroll
                for (int mt = 0; mt < 4; mt++)
#pragma unroll
                    for (int nt = 0; nt < 4; nt++)
                        mma_tf32(acc[mt][nt], au[mt][0], au[mt][1], au[mt][2],
                                 au[mt][3], bu[nt][0], bu[nt][1]);
            } else {
                uint32_t bh[4][2], bl[4][2];
#pragma unroll
                for (int nt = 0; nt < 4; nt++)
#pragma unroll
                    for (int q = 0; q < 2; q++) {
                        float v = __uint_as_float(bu[nt][q]);
                        uint32_t hi = tf32_rna(v);
                        bh[nt][q] = hi;
                        bl[nt][q] = tf32_rna(v - __uint_as_float(hi));
                    }
#pragma unroll
                for (int mt = 0; mt < 4; mt++) {
                    uint32_t ah[4], al[4];
#pragma unroll
                    for (int q = 0; q < 4; q++) {
                        float v = __uint_as_float(au[mt][q]);
                        ah[q] = tf32_rna(v);
                        al[q] = tf32_rna(v - __uint_as_float(ah[q]));
                    }
#pragma unroll
                    for (int nt = 0; nt < 4; nt++) {
                        mma_tf32(acc[mt][nt], al[0], al[1], al[2], al[3],
                                 bh[nt][0], bh[nt][1]);
                        mma_tf32(acc[mt][nt], ah[0], ah[1], ah[2], ah[3],
                                 bl[nt][0], bl[nt][1]);
                        mma_tf32(acc[mt][nt], ah[0], ah[1], ah[2], ah[3],
                                 bh[nt][0], bh[nt][1]);
                    }
                }
            }
        }
        __syncthreads();
        if (t + NSTAGE < nchunk) load_chunk(t + NSTAGE, s);
    }

#pragma unroll
    for (int mt = 0; mt < 4; mt++) {
        const int row = m0 + wm * 64 + mt * 16 + g;
        float* Cr0 = C + (size_t)row * ldc + n0;
        float* Cr1 = Cr0 + 8 * ldc;
#pragma unroll
        for (int nt = 0; nt < 4; nt++) {
            const int col = wn * 32 + nt * 8 + tg * 2;
            float2 v0 = make_float2(acc[mt][nt][0] + bias_s[col],
                                    acc[mt][nt][1] + bias_s[col + 1]);
            float2 v1 = make_float2(acc[mt][nt][2] + bias_s[col],
                                    acc[mt][nt][3] + bias_s[col + 1]);
            *(float2*)(Cr0 + col) = v0;
            *(float2*)(Cr1 + col) = v1;
        }
    }
}

// ---------------- u split-K reduce ------------------------------------------
__global__ __launch_bounds__(256) void ureduce(const float* __restrict__ p,
                                               float* __restrict__ u)
{
    const int i = (blockIdx.x * 256 + threadIdx.x) * 4;
    float4 a = *(const float4*)(p + i);
    float4 b = *(const float4*)(p + NB * NH + i);
    float4 c = *(const float4*)(p + 2 * NB * NH + i);
    float4 d = *(const float4*)(p + 3 * NB * NH + i);
    *(float4*)(u + i) = make_float4(a.x + b.x + c.x + d.x, a.y + b.y + c.y + d.y,
                                    a.z + b.z + c.z + d.z, a.w + b.w + c.w + d.w);
}

// ---------------- attn_W transpose -------------------------------------------
__global__ __launch_bounds__(256) void transpose1024(const float* __restrict__ in,
                                                     float* __restrict__ out)
{
    __shared__ float t[32][33];
    int x = blockIdx.x * 32 + threadIdx.x;
    int y0 = blockIdx.y * 32 + threadIdx.y;
#pragma unroll
    for (int j = 0; j < 32; j += 8)
        t[threadIdx.y + j][threadIdx.x] = in[(size_t)(y0 + j) * NH + x];
    __syncthreads();
    x = blockIdx.y * 32 + threadIdx.x;
    y0 = blockIdx.x * 32 + threadIdx.y;
#pragma unroll
    for (int j = 0; j < 32; j += 8)
        out[(size_t)(y0 + j) * NH + x] = t[threadIdx.x][threadIdx.y + j];
}

// ---------------- repack pre_W [1024,1034] -> [1024,1056] zero-padded -------
__global__ __launch_bounds__(256) void repack_preW(const float* __restrict__ W,
                                                   float* __restrict__ out)
{
    const int n = blockIdx.x;
    for (int k = threadIdx.x; k < CAT_LD; k += 256)
        out[(size_t)n * CAT_LD + k] = (k < NH + NM) ? W[(size_t)n * (NH + NM) + k] : 0.f;
}

__device__ __forceinline__ float warp_sum(float v) {
#pragma unroll
    for (int o = 16; o; o >>= 1) v += __shfl_xor_sync(0xffffffffu, v, o);
    return v;
}

// ---------------- fused single-pass attention (online softmax) --------------
__global__ __launch_bounds__(256, 2) void attn_fused(
    const float* __restrict__ enc, const float* __restrict__ u,
    const float* __restrict__ motion, float* __restrict__ attn_out,
    float* __restrict__ cat)
{
    const int b = blockIdx.x;
    const int tid = threadIdx.x;
    const int lane = tid & 31, w = tid >> 5;

    __shared__ float e_raw[NS];
    __shared__ float warp_m[8], warp_z[8];
    __shared__ __align__(16) float ctxs[8 * NH];

    const float4* u4 = (const float4*)(u + (size_t)b * NH);
    float4 ur[8];
#pragma unroll
    for (int i = 0; i < 8; i++) ur[i] = u4[i * 32 + lane];

    float4 cacc[8];
#pragma unroll
    for (int i = 0; i < 8; i++) cacc[i] = make_float4(0.f, 0.f, 0.f, 0.f);
    float m = -1e30f, Z = 0.f;

#pragma unroll
    for (int si = 0; si < 8; si++) {
        const int s = w + si * 8;
        const float4* ep = (const float4*)(enc + ((size_t)s * NB + b) * NH);
        float4 row[8];
        float d = 0.f;
#pragma unroll
        for (int i = 0; i < 8; i++) {
            row[i] = ep[i * 32 + lane];
            d = fmaf(row[i].x, ur[i].x, d);
            d = fmaf(row[i].y, ur[i].y, d);
            d = fmaf(row[i].z, ur[i].z, d);
            d = fmaf(row[i].w, ur[i].w, d);
        }
        d = warp_sum(d);
        if (lane == 0) e_raw[s] = d;
        const float mn = fmaxf(m, d);
        const float scale = __expf(m - mn);
        const float wgt = __expf(d - mn);
        Z = Z * scale + wgt;
#pragma unroll
        for (int i = 0; i < 8; i++) {
            cacc[i].x = fmaf(cacc[i].x, scale, wgt * row[i].x);
            cacc[i].y = fmaf(cacc[i].y, scale, wgt * row[i].y);
            cacc[i].z = fmaf(cacc[i].z, scale, wgt * row[i].z);
            cacc[i].w = fmaf(cacc[i].w, scale, wgt * row[i].w);
        }
        m = mn;
    }

    if (lane == 0) { warp_m[w] = m; warp_z[w] = Z; }
    float4* cs = (float4*)(ctxs + w * NH);
#pragma unroll
    for (int i = 0; i < 8; i++) cs[i * 32 + lane] = cacc[i];
    __syncthreads();

    float gm = warp_m[0];
#pragma unroll
    for (int ww = 1; ww < 8; ww++) gm = fmaxf(gm, warp_m[ww]);
    float gZ = 0.f;
#pragma unroll
    for (int ww = 0; ww < 8; ww++) gZ += warp_z[ww] * __expf(warp_m[ww] - gm);
    const float invZ = 1.f / gZ;

    if (tid < NS) attn_out[(size_t)b * NS + tid] = __expf(e_raw[tid] - gm) * invZ;
    if (tid < NM) cat[(size_t)b * CAT_LD + tid] = motion[(size_t)b * NM + tid];
    if (tid < CAT_LD - NH - NM)
        cat[(size_t)b * CAT_LD + NH + NM + tid] = 0.f;

    float4 a = make_float4(0.f, 0.f, 0.f, 0.f);
#pragma unroll
    for (int ww = 0; ww < 8; ww++) {
        const float sc = __expf(warp_m[ww] - gm);
        float4 v = *(const float4*)&ctxs[ww * NH + tid * 4];
        a.x = fmaf(v.x, sc, a.x);
        a.y = fmaf(v.y, sc, a.y);
        a.z = fmaf(v.z, sc, a.z);
        a.w = fmaf(v.w, sc, a.w);
    }
    float* cp = cat + (size_t)b * CAT_LD + NM + tid * 4;
    *(float2*)cp       = make_float2(a.x * invZ, a.y * invZ);
    *(float2*)(cp + 2) = make_float2(a.z * invZ, a.w * invZ);
}

// ---------------- GRU gate pointwise ----------------------------------------
__global__ __launch_bounds__(256) void gate_kernel(
    const float* __restrict__ gi, const float* __restrict__ gh,
    const float* __restrict__ hprev, float* __restrict__ out_h)
{
    const int idx = blockIdx.x * blockDim.x + threadIdx.x;
    const int b = idx >> 10, n = idx & (NH - 1);
    const float* gib = gi + (size_t)b * 3 * NH;
    const float* ghb = gh + (size_t)b * 3 * NH;
    float ir = gib[n], iz = gib[NH + n], inn = gib[2 * NH + n];
    float hr = ghb[n], hz = ghb[NH + n], hn = ghb[2 * NH + n];
    float r = 1.f / (1.f + expf(-(ir + hr)));
    float z = 1.f / (1.f + expf(-(iz + hz)));
    float nn = tanhf(inn + r * hn);
    out_h[idx] = (1.f - z) * nn + z * hprev[idx];
}

// ---------------- post linear: [B,1024] -> [B,10] ---------------------------
__global__ __launch_bounds__(128) void post_kernel(
    const float* __restrict__ h1, const float* __restrict__ W,
    const float* __restrict__ bias, float* __restrict__ out)
{
    const int b = blockIdx.x;
    const int tid = threadIdx.x;
    float acc[10];
#pragma unroll
    for (int o = 0; o < 10; o++) acc[o] = 0.f;
    for (int h = tid; h < NH; h += 128) {
        float x = h1[(size_t)b * NH + h];
#pragma unroll
        for (int o = 0; o < 10; o++) acc[o] = fmaf(x, W[(size_t)o * NH + h], acc[o]);
    }
    __shared__ float red[128];
#pragma unroll
    for (int o = 0; o < 10; o++) {
        red[tid] = acc[o];
        __syncthreads();
        for (int st = 64; st; st >>= 1) {
            if (tid < st) red[tid] += red[tid + st];
            __syncthreads();
        }
        if (tid == 0) out[(size_t)b * 10 + o] = red[0] + bias[o];
        __syncthreads();
    }
}

// ---------------- host launch ------------------------------------------------
extern "C" void kernel_launch(void* const* d_in, const int* in_sizes, int n_in,
                              void* d_out, int out_size)
{
    const float* motion      = (const float*)d_in[0];
    const float* last_hidden = (const float*)d_in[1];
    const float* enc         = (const float*)d_in[2];
    const float* attn_W      = (const float*)d_in[3];
    /* d_in[4] = attn_b: unused (softmax shift-invariant) */
    const float* pre_W  = (const float*)d_in[5];
    const float* pre_b  = (const float*)d_in[6];
    const float* Wih0   = (const float*)d_in[7];
    const float* Whh0   = (const float*)d_in[8];
    const float* bih0   = (const float*)d_in[9];
    const float* bhh0   = (const float*)d_in[10];
    const float* Wih1   = (const float*)d_in[11];
    const float* Whh1   = (const float*)d_in[12];
    const float* bih1   = (const float*)d_in[13];
    const float* bhh1   = (const float*)d_in[14];
    const float* post_W = (const float*)d_in[15];
    const float* post_b = (const float*)d_in[16];

    float* out        = (float*)d_out;
    float* out_output = out;
    float* out_h0     = out + NB * 10;
    float* out_h1     = out + NB * 10 + NB * NH;
    float* out_attn   = out + NB * 10 + 2 * NB * NH;

    float *u, *upart, *cat, *x0, *gi, *gh0, *gh1, *preW, *Wt;
    cudaGetSymbolAddress((void**)&u,     g_u);
    cudaGetSymbolAddress((void**)&upart, g_upart);
    cudaGetSymbolAddress((void**)&cat,   g_cat);
    cudaGetSymbolAddress((void**)&x0,    g_x0);
    cudaGetSymbolAddress((void**)&gi,    g_gi);
    cudaGetSymbolAddress((void**)&gh0,   g_gh0);
    cudaGetSymbolAddress((void**)&gh1,   g_gh1);
    cudaGetSymbolAddress((void**)&preW,  g_preW);
    cudaGetSymbolAddress((void**)&Wt,    g_Wt);

    const float* hL0 = last_hidden;
    const float* hL1 = last_hidden + NB * NH;

    cudaFuncSetAttribute(gemm_mma, cudaFuncAttributeMaxDynamicSharedMemorySize,
                         DYN_SMEM);

    // 0) weight repacks (independent, ~2-3us)
    transpose1024<<<dim3(32, 32), dim3(32, 8)>>>(attn_W, Wt);
    repack_preW<<<NH, 256>>>(pre_W, preW);

    // 1) combo: u split-K x4 (split-tf32) + gh0 + gh1 in one launch
    {
        Jobs j = {};
        for (int s = 0; s < 4; s++) {
            j.A[s] = hL1 + s * 256;  j.B[s] = Wt + s * 256;
            j.bias[s] = nullptr;     j.C[s] = upart + (size_t)s * NB * NH;
            j.lda[s] = NH; j.ldb[s] = NH; j.ldc[s] = NH;
            j.nchunk[s] = 16; j.nx[s] = 8; j.split[s] = 1;
        }
        j.A[4] = hL0; j.B[4] = Whh0; j.bias[4] = bhh0; j.C[4] = gh0;
        j.lda[4] = NH; j.ldb[4] = NH; j.ldc[4] = 3 * NH;
        j.nchunk[4] = 64; j.nx[4] = 24; j.split[4] = 0;
        j.A[5] = hL1; j.B[5] = Whh1; j.bias[5] = bhh1; j.C[5] = gh1;
        j.lda[5] = NH; j.ldb[5] = NH; j.ldc[5] = 3 * NH;
        j.nchunk[5] = 64; j.nx[5] = 24; j.split[5] = 0;
        gemm_mma<<<dim3(24, 4, 6), 256, DYN_SMEM>>>(j);
    }
    ureduce<<<NB * NH / 1024, 256>>>(upart, u);

    // 2) fused single-pass attention (enc read once)
    attn_fused<<<NB, 256>>>(enc, u, motion, out_attn, cat);

    // 3) rnn_input = cat @ preW^T + pre_b
    {
        Jobs j = {};
        j.A[0] = cat; j.B[0] = preW; j.bias[0] = pre_b; j.C[0] = x0;
        j.lda[0] = CAT_LD; j.ldb[0] = CAT_LD; j.ldc[0] = NH;
        j.nchunk[0] = 66; j.nx[0] = 8; j.split[0] = 0;
        gemm_mma<<<dim3(8, 4, 1), 256, DYN_SMEM>>>(j);
    }

    // 4) GRU layer 0: gi (gh0 already done)
    {
        Jobs j = {};
        j.A[0] = x0; j.B[0] = Wih0; j.bias[0] = bih0; j.C[0] = gi;
        j.lda[0] = NH; j.ldb[0] = NH; j.ldc[0] = 3 * NH;
        j.nchunk[0] = 64; j.nx[0] = 24; j.split[0] = 0;
        gemm_mma<<<dim3(24, 4, 1), 256, DYN_SMEM>>>(j);
    }
    gate_kernel<<<NB * NH / 256, 256>>>(gi, gh0, hL0, out_h0);

    // 5) GRU layer 1
    {
        Jobs j = {};
        j.A[0] = out_h0; j.B[0] = Wih1; j.bias[0] = bih1; j.C[0] = gi;
        j.lda[0] = NH; j.ldb[0] = NH; j.ldc[0] = 3 * NH;
        j.nchunk[0] = 64; j.nx[0] = 24; j.split[0] = 0;
        gemm_mma<<<dim3(24, 4, 1), 256, DYN_SMEM>>>(j);
    }
    gate_kernel<<<NB * NH / 256, 256>>>(gi, gh1, hL1, out_h1);

    // 6) output = h1 @ post_W^T + post_b
    post_kernel<<<NB, 128>>>(out_h1, post_W, post_b, out_output);
}

// round 7
// speedup vs baseline: 2.9738x; 1.0599x over previous
#include <cuda_runtime.h>
#include <math.h>
#include <stdint.h>

#define NB 512
#define NH 1024
#define NS 64
#define NM 10
#define CAT_LD 1056   // 66 chunks of 16 (K padded, zero-filled)
#define NJOBS 6

// ---------------- scratch (device globals; no allocations allowed) ----------
__device__ __align__(1024) float g_upart[4 * NB * NH];
__device__ __align__(1024) float g_xpart[3 * NB * NH];
__device__ __align__(1024) float g_cat[NB * CAT_LD];
__device__ __align__(1024) float g_x0[NB * NH];
__device__ __align__(1024) float g_gi[NB * 3 * NH];
__device__ __align__(1024) float g_gh0[NB * 3 * NH];
__device__ __align__(1024) float g_gh1[NB * 3 * NH];
__device__ __align__(1024) float g_preW[NH * CAT_LD];
__device__ __align__(1024) float g_Wt[NH * NH];       // attn_W transposed

struct Jobs {
    const float* A[NJOBS]; const float* B[NJOBS];
    const float* bias[NJOBS]; float* C[NJOBS];
    int lda[NJOBS], ldb[NJOBS], ldc[NJOBS], nchunk[NJOBS], nx[NJOBS], split[NJOBS];
};

// ---------------- helpers ----------------------------------------------------
__device__ __forceinline__ uint32_t smem_u32(const void* p) {
    uint32_t a;
    asm("{ .reg .u64 t; cvta.to.shared.u64 t, %1; cvt.u32.u64 %0, t; }"
        : "=r"(a) : "l"(p));
    return a;
}
__device__ __forceinline__ uint32_t tf32_rna(float x) {
    uint32_t r;
    asm("cvt.rna.tf32.f32 %0, %1;" : "=r"(r) : "f"(x));
    return r;
}
__device__ __forceinline__ void mma_tf32(float* c, uint32_t a0, uint32_t a1,
                                         uint32_t a2, uint32_t a3,
                                         uint32_t b0, uint32_t b1) {
    asm volatile(
        "mma.sync.aligned.m16n8k8.row.col.f32.tf32.tf32.f32 "
        "{%0,%1,%2,%3}, {%4,%5,%6,%7}, {%8,%9}, {%0,%1,%2,%3};"
        : "+f"(c[0]), "+f"(c[1]), "+f"(c[2]), "+f"(c[3])
        : "r"(a0), "r"(a1), "r"(a2), "r"(a3), "r"(b0), "r"(b1));
}
__device__ __forceinline__ void cp16(uint32_t dst, const void* src) {
    asm volatile("cp.async.cg.shared.global [%0], [%1], 16;"
                 :: "r"(dst), "l"(src));
}
__device__ __forceinline__ void ldsm4(uint32_t& r0, uint32_t& r1, uint32_t& r2,
                                      uint32_t& r3, uint32_t addr) {
    asm volatile("ldmatrix.sync.aligned.m8n8.x4.shared.b16 {%0,%1,%2,%3}, [%4];"
                 : "=r"(r0), "=r"(r1), "=r"(r2), "=r"(r3) : "r"(addr));
}

// ---------------- tf32 warp-MMA GEMM (job-table batched) --------------------
#define NSTAGE 3
#define STG_F (2 * 128 * 20)
#define DYN_SMEM (NSTAGE * STG_F * 4)     // 61440 B

__global__ __launch_bounds__(256, 2) void gemm_mma(Jobs jobs)
{
    const int z = blockIdx.z;
    if (blockIdx.x >= jobs.nx[z]) return;

    extern __shared__ float dyn[];
    __shared__ float bias_s[128];

    const float* A = jobs.A[z];
    const float* B = jobs.B[z];
    const float* bias = jobs.bias[z];
    float* C = jobs.C[z];
    const int lda = jobs.lda[z], ldb = jobs.ldb[z], ldc = jobs.ldc[z];
    const int nchunk = jobs.nchunk[z], split = jobs.split[z];

    const int tid = threadIdx.x;
    const int wid = tid >> 5, lane = tid & 31;
    const int g = lane >> 2, tg = lane & 3;
    const int wm = wid >> 2, wn = wid & 3;
    const int lr = lane & 7, lq = lane >> 3;
    const int n0 = blockIdx.x * 128;
    const int m0 = blockIdx.y * 128;

    if (tid < 128) bias_s[tid] = bias ? bias[n0 + tid] : 0.f;

    const uint32_t smem_base = smem_u32(dyn);
    const uint32_t a_off = (uint32_t)(((wm * 64 + (lq & 1) * 8 + lr) * 20 +
                                      (lq >> 1) * 4) * 4);
    const uint32_t b_off = (uint32_t)((2560 + (wn * 32 + (lq >> 1) * 8 + lr) * 20 +
                                      (lq & 1) * 4) * 4);

    const int lr0 = tid >> 2,          lk0 = tid & 3;
    const int lr1 = (tid + 256) >> 2,  lk1 = (tid + 256) & 3;

    auto load_chunk = [&](int c, int s) {
        const uint32_t sa = smem_base + s * (STG_F * 4);
        const uint32_t sb = sa + 2560 * 4;
        const float* Ag = A + (size_t)m0 * lda + c * 16;
        const float* Bg = B + (size_t)n0 * ldb + c * 16;
        cp16(sa + (lr0 * 20 + lk0 * 4) * 4, Ag + (size_t)lr0 * lda + lk0 * 4);
        cp16(sa + (lr1 * 20 + lk1 * 4) * 4, Ag + (size_t)lr1 * lda + lk1 * 4);
        cp16(sb + (lr0 * 20 + lk0 * 4) * 4, Bg + (size_t)lr0 * ldb + lk0 * 4);
        cp16(sb + (lr1 * 20 + lk1 * 4) * 4, Bg + (size_t)lr1 * ldb + lk1 * 4);
        asm volatile("cp.async.commit_group;" ::: "memory");
    };

    float acc[4][4][4];
#pragma unroll
    for (int mt = 0; mt < 4; mt++)
#pragma unroll
        for (int nt = 0; nt < 4; nt++)
#pragma unroll
            for (int q = 0; q < 4; q++) acc[mt][nt][q] = 0.f;

#pragma unroll
    for (int s = 0; s < NSTAGE; s++) load_chunk(s, s);

    for (int t = 0; t < nchunk; t++) {
        const int s = t % NSTAGE;
        asm volatile("cp.async.wait_group 2;" ::: "memory");
        __syncthreads();

        const uint32_t sbase = smem_base + s * (STG_F * 4);
        const uint32_t abase = sbase + a_off;
        const uint32_t bbase = sbase + b_off;

#pragma unroll
        for (int ks = 0; ks < 2; ks++) {
            uint32_t au[4][4], bu[4][2];
#pragma unroll
            for (int mt = 0; mt < 4; mt++)
                ldsm4(au[mt][0], au[mt][1], au[mt][2], au[mt][3],
                      abase + mt * 1280 + ks * 32);
#pragma unroll
            for (int j = 0; j < 2; j++)
                ldsm4(bu[2 * j][0], bu[2 * j][1], bu[2 * j + 1][0],
                      bu[2 * j + 1][1], bbase + j * 1280 + ks * 32);

            if (!split) {
#pragma unroll
                for (int mt = 0; mt < 4; mt++)
#pragma unroll
                    for (int nt = 0; nt < 4; nt++)
                        mma_tf32(acc[mt][nt], au[mt][0], au[mt][1], au[mt][2],
                                 au[mt][3], bu[nt][0], bu[nt][1]);
            } else {
                uint32_t bh[4][2], bl[4][2];
#pragma unroll
                for (int nt = 0; nt < 4; nt++)
#pragma unroll
                    for (int q = 0; q < 2; q++) {
                        float v = __uint_as_float(bu[nt][q]);
                        uint32_t hi = tf32_rna(v);
                        bh[nt][q] = hi;
                        bl[nt][q] = tf32_rna(v - __uint_as_float(hi));
                    }
#pragma unroll
                for (int mt = 0; mt < 4; mt++) {
                    uint32_t ah[4], al[4];
#pragma unroll
                    for (int q = 0; q < 4; q++) {
                        float v = __uint_as_float(au[mt][q]);
                        ah[q] = tf32_rna(v);
                        al[q] = tf32_rna(v - __uint_as_float(ah[q]));
                    }
#pragma unroll
                    for (int nt = 0; nt < 4; nt++) {
                        mma_tf32(acc[mt][nt], al[0], al[1], al[2], al[3],
                                 bh[nt][0], bh[nt][1]);
                        mma_tf32(acc[mt][nt], ah[0], ah[1], ah[2], ah[3],
                                 bl[nt][0], bl[nt][1]);
                        mma_tf32(acc[mt][nt], ah[0], ah[1], ah[2], ah[3],
                                 bh[nt][0], bh[nt][1]);
                    }
                }
            }
        }
        __syncthreads();
        if (t + NSTAGE < nchunk) load_chunk(t + NSTAGE, s);
    }

#pragma unroll
    for (int mt = 0; mt < 4; mt++) {
        const int row = m0 + wm * 64 + mt * 16 + g;
        float* Cr0 = C + (size_t)row * ldc + n0;
        float* Cr1 = Cr0 + 8 * ldc;
#pragma unroll
        for (int nt = 0; nt < 4; nt++) {
            const int col = wn * 32 + nt * 8 + tg * 2;
            float2 v0 = make_float2(acc[mt][nt][0] + bias_s[col],
                                    acc[mt][nt][1] + bias_s[col + 1]);
            float2 v1 = make_float2(acc[mt][nt][2] + bias_s[col],
                                    acc[mt][nt][3] + bias_s[col + 1]);
            *(float2*)(Cr0 + col) = v0;
            *(float2*)(Cr1 + col) = v1;
        }
    }
}

// ---------------- prep: attn_W transpose + pre_W repack (one launch) --------
__global__ __launch_bounds__(256) void prep_kernel(
    const float* __restrict__ attn_W, float* __restrict__ Wt,
    const float* __restrict__ pre_W, float* __restrict__ preW)
{
    if (blockIdx.y < 32) {
        __shared__ float t[32][33];
        const int tx = threadIdx.x & 31, ty = threadIdx.x >> 5;
        int x = blockIdx.x * 32 + tx;
        int y0 = blockIdx.y * 32 + ty;
#pragma unroll
        for (int j = 0; j < 32; j += 8)
            t[ty + j][tx] = attn_W[(size_t)(y0 + j) * NH + x];
        __syncthreads();
        x = blockIdx.y * 32 + tx;
        y0 = blockIdx.x * 32 + ty;
#pragma unroll
        for (int j = 0; j < 32; j += 8)
            Wt[(size_t)(y0 + j) * NH + x] = t[tx][ty + j];
    } else {
        const int n = (blockIdx.y - 32) * 32 + blockIdx.x;
        for (int k = threadIdx.x; k < CAT_LD; k += 256)
            preW[(size_t)n * CAT_LD + k] =
                (k < NH + NM) ? pre_W[(size_t)n * (NH + NM) + k] : 0.f;
    }
}

__device__ __forceinline__ float warp_sum(float v) {
#pragma unroll
    for (int o = 16; o; o >>= 1) v += __shfl_xor_sync(0xffffffffu, v, o);
    return v;
}

// ---------------- fused attention: u-reduce + online softmax + context ------
__global__ __launch_bounds__(256, 3) void attn_fused(
    const float* __restrict__ enc, const float* __restrict__ upart,
    const float* __restrict__ motion, float* __restrict__ attn_out,
    float* __restrict__ cat)
{
    const int b = blockIdx.x;
    const int tid = threadIdx.x;
    const int lane = tid & 31, w = tid >> 5;

    __shared__ float e_raw[NS];
    __shared__ float warp_m[8], warp_z[8];
    __shared__ __align__(16) float ur_s[NH];
    __shared__ __align__(16) float ctxs[8 * NH];

    // fold the u split-K reduce in here (u row b = sum of 4 partial rows)
    {
        const float4* p0 = (const float4*)(upart + (size_t)b * NH);
        const float4* p1 = (const float4*)(upart + (size_t)NB * NH + (size_t)b * NH);
        const float4* p2 = (const float4*)(upart + 2 * (size_t)NB * NH + (size_t)b * NH);
        const float4* p3 = (const float4*)(upart + 3 * (size_t)NB * NH + (size_t)b * NH);
        float4 a = p0[tid], c = p1[tid], d = p2[tid], e = p3[tid];
        ((float4*)ur_s)[tid] = make_float4(a.x + c.x + d.x + e.x,
                                           a.y + c.y + d.y + e.y,
                                           a.z + c.z + d.z + e.z,
                                           a.w + c.w + d.w + e.w);
    }
    __syncthreads();

    float4 cacc[8];
#pragma unroll
    for (int i = 0; i < 8; i++) cacc[i] = make_float4(0.f, 0.f, 0.f, 0.f);
    float m = -1e30f, Z = 0.f;
    const float4* u4 = (const float4*)ur_s;

#pragma unroll
    for (int si = 0; si < 8; si++) {
        const int s = w + si * 8;
        const float4* ep = (const float4*)(enc + ((size_t)s * NB + b) * NH);
        float4 row[8];
        float d = 0.f;
#pragma unroll
        for (int i = 0; i < 8; i++) {
            row[i] = ep[i * 32 + lane];
            float4 uv = u4[i * 32 + lane];
            d = fmaf(row[i].x, uv.x, d);
            d = fmaf(row[i].y, uv.y, d);
            d = fmaf(row[i].z, uv.z, d);
            d = fmaf(row[i].w, uv.w, d);
        }
        d = warp_sum(d);
        if (lane == 0) e_raw[s] = d;
        const float mn = fmaxf(m, d);
        const float scale = __expf(m - mn);
        const float wgt = __expf(d - mn);
        Z = Z * scale + wgt;
#pragma unroll
        for (int i = 0; i < 8; i++) {
            cacc[i].x = fmaf(cacc[i].x, scale, wgt * row[i].x);
            cacc[i].y = fmaf(cacc[i].y, scale, wgt * row[i].y);
            cacc[i].z = fmaf(cacc[i].z, scale, wgt * row[i].z);
            cacc[i].w = fmaf(cacc[i].w, scale, wgt * row[i].w);
        }
        m = mn;
    }

    if (lane == 0) { warp_m[w] = m; warp_z[w] = Z; }
    float4* cs = (float4*)(ctxs + w * NH);
#pragma unroll
    for (int i = 0; i < 8; i++) cs[i * 32 + lane] = cacc[i];
    __syncthreads();

    float gm = warp_m[0];
#pragma unroll
    for (int ww = 1; ww < 8; ww++) gm = fmaxf(gm, warp_m[ww]);
    float gZ = 0.f;
#pragma unroll
    for (int ww = 0; ww < 8; ww++) gZ += warp_z[ww] * __expf(warp_m[ww] - gm);
    const float invZ = 1.f / gZ;

    if (tid < NS) attn_out[(size_t)b * NS + tid] = __expf(e_raw[tid] - gm) * invZ;
    if (tid < NM) cat[(size_t)b * CAT_LD + tid] = motion[(size_t)b * NM + tid];
    if (tid < CAT_LD - NH - NM)
        cat[(size_t)b * CAT_LD + NH + NM + tid] = 0.f;

    float4 a = make_float4(0.f, 0.f, 0.f, 0.f);
#pragma unroll
    for (int ww = 0; ww < 8; ww++) {
        const float sc = __expf(warp_m[ww] - gm);
        float4 v = *(const float4*)&ctxs[ww * NH + tid * 4];
        a.x = fmaf(v.x, sc, a.x);
        a.y = fmaf(v.y, sc, a.y);
        a.z = fmaf(v.z, sc, a.z);
        a.w = fmaf(v.w, sc, a.w);
    }
    float* cp = cat + (size_t)b * CAT_LD + NM + tid * 4;
    *(float2*)cp       = make_float2(a.x * invZ, a.y * invZ);
    *(float2*)(cp + 2) = make_float2(a.z * invZ, a.w * invZ);
}

// ---------------- x0 split-K reduce (3 partials, bias already in slice 0) ---
__global__ __launch_bounds__(256) void xreduce(const float* __restrict__ p,
                                               float* __restrict__ x0)
{
    const int i = (blockIdx.x * 256 + threadIdx.x) * 4;
    float4 a = *(const float4*)(p + i);
    float4 b = *(const float4*)(p + (size_t)NB * NH + i);
    float4 c = *(const float4*)(p + 2 * (size_t)NB * NH + i);
    *(float4*)(x0 + i) = make_float4(a.x + b.x + c.x, a.y + b.y + c.y,
                                     a.z + b.z + c.z, a.w + b.w + c.w);
}

// ---------------- GRU gate pointwise (layer 0) ------------------------------
__global__ __launch_bounds__(256) void gate_kernel(
    const float* __restrict__ gi, const float* __restrict__ gh,
    const float* __restrict__ hprev, float* __restrict__ out_h)
{
    const int idx = blockIdx.x * blockDim.x + threadIdx.x;
    const int b = idx >> 10, n = idx & (NH - 1);
    const float* gib = gi + (size_t)b * 3 * NH;
    const float* ghb = gh + (size_t)b * 3 * NH;
    float ir = gib[n], iz = gib[NH + n], inn = gib[2 * NH + n];
    float hr = ghb[n], hz = ghb[NH + n], hn = ghb[2 * NH + n];
    float r = 1.f / (1.f + expf(-(ir + hr)));
    float z = 1.f / (1.f + expf(-(iz + hz)));
    float nn = tanhf(inn + r * hn);
    out_h[idx] = (1.f - z) * nn + z * hprev[idx];
}

// ---------------- fused gate(layer 1) + post linear -------------------------
// 1 block per batch row: compute h1 (4 elems/thread), write it, then the
// 10-way output dot with the h1 values still in registers.
__global__ __launch_bounds__(256) void gatepost_kernel(
    const float* __restrict__ gi, const float* __restrict__ gh,
    const float* __restrict__ hprev, float* __restrict__ out_h,
    const float* __restrict__ W, const float* __restrict__ bias,
    float* __restrict__ out)
{
    const int b = blockIdx.x;
    const int tid = threadIdx.x;
    const float* gib = gi + (size_t)b * 3 * NH;
    const float* ghb = gh + (size_t)b * 3 * NH;

    float hv[4];
#pragma unroll
    for (int q = 0; q < 4; q++) {
        const int n = tid * 4 + q;
        float ir = gib[n], iz = gib[NH + n], inn = gib[2 * NH + n];
        float hr = ghb[n], hz = ghb[NH + n], hn = ghb[2 * NH + n];
        float r = 1.f / (1.f + expf(-(ir + hr)));
        float z = 1.f / (1.f + expf(-(iz + hz)));
        float nn = tanhf(inn + r * hn);
        hv[q] = (1.f - z) * nn + z * hprev[(size_t)b * NH + n];
    }
    *(float4*)(out_h + (size_t)b * NH + tid * 4) =
        make_float4(hv[0], hv[1], hv[2], hv[3]);

    float acc[10];
#pragma unroll
    for (int o = 0; o < 10; o++) {
        const float4 wv = *(const float4*)(W + (size_t)o * NH + tid * 4);
        acc[o] = hv[0] * wv.x + hv[1] * wv.y + hv[2] * wv.z + hv[3] * wv.w;
    }
    __shared__ float red[10][8];
    const int lane = tid & 31, w = tid >> 5;
#pragma unroll
    for (int o = 0; o < 10; o++) {
        float v = warp_sum(acc[o]);
        if (lane == 0) red[o][w] = v;
    }
    __syncthreads();
    if (tid < 10) {
        float s = 0.f;
#pragma unroll
        for (int ww = 0; ww < 8; ww++) s += red[tid][ww];
        out[(size_t)b * 10 + tid] = s + bias[tid];
    }
}

// ---------------- host launch ------------------------------------------------
extern "C" void kernel_launch(void* const* d_in, const int* in_sizes, int n_in,
                              void* d_out, int out_size)
{
    const float* motion      = (const float*)d_in[0];
    const float* last_hidden = (const float*)d_in[1];
    const float* enc         = (const float*)d_in[2];
    const float* attn_W      = (const float*)d_in[3];
    /* d_in[4] = attn_b: unused (softmax shift-invariant) */
    const float* pre_W  = (const float*)d_in[5];
    const float* pre_b  = (const float*)d_in[6];
    const float* Wih0   = (const float*)d_in[7];
    const float* Whh0   = (const float*)d_in[8];
    const float* bih0   = (const float*)d_in[9];
    const float* bhh0   = (const float*)d_in[10];
    const float* Wih1   = (const float*)d_in[11];
    const float* Whh1   = (const float*)d_in[12];
    const float* bih1   = (const float*)d_in[13];
    const float* bhh1   = (const float*)d_in[14];
    const float* post_W = (const float*)d_in[15];
    const float* post_b = (const float*)d_in[16];

    float* out        = (float*)d_out;
    float* out_output = out;
    float* out_h0     = out + NB * 10;
    float* out_h1     = out + NB * 10 + NB * NH;
    float* out_attn   = out + NB * 10 + 2 * NB * NH;

    float *upart, *xpart, *cat, *x0, *gi, *gh0, *gh1, *preW, *Wt;
    cudaGetSymbolAddress((void**)&upart, g_upart);
    cudaGetSymbolAddress((void**)&xpart, g_xpart);
    cudaGetSymbolAddress((void**)&cat,   g_cat);
    cudaGetSymbolAddress((void**)&x0,    g_x0);
    cudaGetSymbolAddress((void**)&gi,    g_gi);
    cudaGetSymbolAddress((void**)&gh0,   g_gh0);
    cudaGetSymbolAddress((void**)&gh1,   g_gh1);
    cudaGetSymbolAddress((void**)&preW,  g_preW);
    cudaGetSymbolAddress((void**)&Wt,    g_Wt);

    const float* hL0 = last_hidden;
    const float* hL1 = last_hidden + NB * NH;

    cudaFuncSetAttribute(gemm_mma, cudaFuncAttributeMaxDynamicSharedMemorySize,
                         DYN_SMEM);

    // 0) prep: transpose attn_W + repack pre_W (one launch)
    prep_kernel<<<dim3(32, 64), 256>>>(attn_W, Wt, pre_W, preW);

    // 1) combo: u split-K x4 (split-tf32) + gh0 + gh1 in one launch
    {
        Jobs j = {};
        for (int s = 0; s < 4; s++) {
            j.A[s] = hL1 + s * 256;  j.B[s] = Wt + s * 256;
            j.bias[s] = nullptr;     j.C[s] = upart + (size_t)s * NB * NH;
            j.lda[s] = NH; j.ldb[s] = NH; j.ldc[s] = NH;
            j.nchunk[s] = 16; j.nx[s] = 8; j.split[s] = 1;
        }
        j.A[4] = hL0; j.B[4] = Whh0; j.bias[4] = bhh0; j.C[4] = gh0;
        j.lda[4] = NH; j.ldb[4] = NH; j.ldc[4] = 3 * NH;
        j.nchunk[4] = 64; j.nx[4] = 24; j.split[4] = 0;
        j.A[5] = hL1; j.B[5] = Whh1; j.bias[5] = bhh1; j.C[5] = gh1;
        j.lda[5] = NH; j.ldb[5] = NH; j.ldc[5] = 3 * NH;
        j.nchunk[5] = 64; j.nx[5] = 24; j.split[5] = 0;
        gemm_mma<<<dim3(24, 4, 6), 256, DYN_SMEM>>>(j);
    }

    // 2) fused attention: u-reduce + single-pass softmax/context
    attn_fused<<<NB, 256>>>(enc, upart, motion, out_attn, cat);

    // 3) rnn_input: split-K x3 (22 chunks each), bias folded into slice 0
    {
        Jobs j = {};
        for (int s = 0; s < 3; s++) {
            j.A[s] = cat + s * 352;  j.B[s] = preW + s * 352;
            j.bias[s] = (s == 0) ? pre_b : nullptr;
            j.C[s] = xpart + (size_t)s * NB * NH;
            j.lda[s] = CAT_LD; j.ldb[s] = CAT_LD; j.ldc[s] = NH;
            j.nchunk[s] = 22; j.nx[s] = 8; j.split[s] = 0;
        }
        gemm_mma<<<dim3(8, 4, 3), 256, DYN_SMEM>>>(j);
    }
    xreduce<<<NB * NH / 1024, 256>>>(xpart, x0);

    // 4) GRU layer 0: gi (gh0 already done), then gate
    {
        Jobs j = {};
        j.A[0] = x0; j.B[0] = Wih0; j.bias[0] = bih0; j.C[0] = gi;
        j.lda[0] = NH; j.ldb[0] = NH; j.ldc[0] = 3 * NH;
        j.nchunk[0] = 64; j.nx[0] = 24; j.split[0] = 0;
        gemm_mma<<<dim3(24, 4, 1), 256, DYN_SMEM>>>(j);
    }
    gate_kernel<<<NB * NH / 256, 256>>>(gi, gh0, hL0, out_h0);

    // 5) GRU layer 1: gi, then fused gate+post
    {
        Jobs j = {};
        j.A[0] = out_h0; j.B[0] = Wih1; j.bias[0] = bih1; j.C[0] = gi;
        j.lda[0] = NH; j.ldb[0] = NH; j.ldc[0] = 3 * NH;
        j.nchunk[0] = 64; j.nx[0] = 24; j.split[0] = 0;
        gemm_mma<<<dim3(24, 4, 1), 256, DYN_SMEM>>>(j);
    }
    gatepost_kernel<<<NB, 256>>>(gi, gh1, hL1, out_h1, post_W, post_b,
                                 out_output);
}